// round 1
// baseline (speedup 1.0000x reference)
#include <cuda_runtime.h>
#include <math.h>

#define SEQ 2048
#define DMODEL 1024
#define NH 16
#define HDK 64

// Scratch (allocation-free contract: __device__ globals)
__device__ float g_q[NH * SEQ * HDK];
__device__ float g_k[NH * SEQ * HDK];
__device__ float g_v[NH * SEQ * HDK];
__device__ float g_concat[SEQ * DMODEL];

// ---------------------------------------------------------------------------
// Projection GEMM: C[h][s][k] = sum_d A[s][d] * W[h][d][k] + b[h][k]
// Tile: BM=128 rows, BN=64 cols (one head), BK=16. 256 threads, 8x4 per thread.
// ---------------------------------------------------------------------------
__global__ __launch_bounds__(256, 4)
void proj_kernel(const float* __restrict__ Qin, const float* __restrict__ Kin,
                 const float* __restrict__ Vin,
                 const float* __restrict__ Wq, const float* __restrict__ Wk,
                 const float* __restrict__ Wv,
                 const float* __restrict__ bq, const float* __restrict__ bk,
                 const float* __restrict__ bv)
{
    const int rowTile = blockIdx.x;   // 0..15
    const int h       = blockIdx.y;   // 0..15
    const int z       = blockIdx.z;   // 0..2

    const float* A; const float* W; const float* bias; float* C;
    if (z == 0)      { A = Qin; W = Wq; bias = bq; C = g_q; }
    else if (z == 1) { A = Kin; W = Wk; bias = bk; C = g_k; }
    else             { A = Vin; W = Wv; bias = bv; C = g_v; }
    W    += (size_t)h * DMODEL * HDK;   // [1024][64] row-major
    bias += h * HDK;
    C    += (size_t)h * SEQ * HDK;      // [2048][64]

    __shared__ float AsT[16][132];      // K-major transposed A tile
    __shared__ float Bs[16][64];

    const int tid = threadIdx.x;
    const int ty = tid >> 4, tx = tid & 15;
    const int row0 = rowTile * 128;

    float acc[8][4];
    #pragma unroll
    for (int i = 0; i < 8; i++)
        #pragma unroll
        for (int j = 0; j < 4; j++) acc[i][j] = 0.f;

    for (int k0 = 0; k0 < DMODEL; k0 += 16) {
        // A tile [128][16] -> AsT[k][r]
        #pragma unroll
        for (int i = 0; i < 2; i++) {
            int idx = tid + i * 256;               // 0..511 float4s
            int r = idx >> 2, c4 = (idx & 3) * 4;
            float4 v4 = *(const float4*)&A[(size_t)(row0 + r) * DMODEL + k0 + c4];
            AsT[c4 + 0][r] = v4.x; AsT[c4 + 1][r] = v4.y;
            AsT[c4 + 2][r] = v4.z; AsT[c4 + 3][r] = v4.w;
        }
        // B tile [16][64]
        {
            int r = tid >> 4, c4 = (tid & 15) * 4;
            *(float4*)&Bs[r][c4] = *(const float4*)&W[(size_t)(k0 + r) * HDK + c4];
        }
        __syncthreads();

        #pragma unroll
        for (int kk = 0; kk < 16; kk++) {
            float af[8], bf[4];
            *(float4*)&af[0] = *(const float4*)&AsT[kk][ty * 8];
            *(float4*)&af[4] = *(const float4*)&AsT[kk][ty * 8 + 4];
            *(float4*)&bf[0] = *(const float4*)&Bs[kk][tx * 4];
            #pragma unroll
            for (int i = 0; i < 8; i++)
                #pragma unroll
                for (int j = 0; j < 4; j++)
                    acc[i][j] = fmaf(af[i], bf[j], acc[i][j]);
        }
        __syncthreads();
    }

    #pragma unroll
    for (int i = 0; i < 8; i++) {
        int r = row0 + ty * 8 + i;
        #pragma unroll
        for (int j = 0; j < 4; j++) {
            int c = tx * 4 + j;
            C[(size_t)r * HDK + c] = acc[i][j] + bias[c];
        }
    }
}

// ---------------------------------------------------------------------------
// Output projection: out = concat @ Wo + bo   (2048x1024 @ 1024x1024)
// ---------------------------------------------------------------------------
__global__ __launch_bounds__(256, 4)
void outproj_kernel(const float* __restrict__ Wo, const float* __restrict__ bo,
                    float* __restrict__ out)
{
    const int rowTile = blockIdx.x;   // 0..15
    const int colTile = blockIdx.y;   // 0..15
    const int n0 = colTile * 64;

    __shared__ float AsT[16][132];
    __shared__ float Bs[16][64];

    const int tid = threadIdx.x;
    const int ty = tid >> 4, tx = tid & 15;
    const int row0 = rowTile * 128;

    float acc[8][4];
    #pragma unroll
    for (int i = 0; i < 8; i++)
        #pragma unroll
        for (int j = 0; j < 4; j++) acc[i][j] = 0.f;

    for (int k0 = 0; k0 < DMODEL; k0 += 16) {
        #pragma unroll
        for (int i = 0; i < 2; i++) {
            int idx = tid + i * 256;
            int r = idx >> 2, c4 = (idx & 3) * 4;
            float4 v4 = *(const float4*)&g_concat[(size_t)(row0 + r) * DMODEL + k0 + c4];
            AsT[c4 + 0][r] = v4.x; AsT[c4 + 1][r] = v4.y;
            AsT[c4 + 2][r] = v4.z; AsT[c4 + 3][r] = v4.w;
        }
        {
            int r = tid >> 4, c4 = (tid & 15) * 4;
            *(float4*)&Bs[r][c4] = *(const float4*)&Wo[(size_t)(k0 + r) * DMODEL + n0 + c4];
        }
        __syncthreads();

        #pragma unroll
        for (int kk = 0; kk < 16; kk++) {
            float af[8], bf[4];
            *(float4*)&af[0] = *(const float4*)&AsT[kk][ty * 8];
            *(float4*)&af[4] = *(const float4*)&AsT[kk][ty * 8 + 4];
            *(float4*)&bf[0] = *(const float4*)&Bs[kk][tx * 4];
            #pragma unroll
            for (int i = 0; i < 8; i++)
                #pragma unroll
                for (int j = 0; j < 4; j++)
                    acc[i][j] = fmaf(af[i], bf[j], acc[i][j]);
        }
        __syncthreads();
    }

    #pragma unroll
    for (int i = 0; i < 8; i++) {
        int r = row0 + ty * 8 + i;
        #pragma unroll
        for (int j = 0; j < 4; j++) {
            int c = n0 + tx * 4 + j;
            out[(size_t)r * DMODEL + c] = acc[i][j] + bo[c];
        }
    }
}

// ---------------------------------------------------------------------------
// Flash attention (fp32, online softmax). Block = (64 q-rows) x (one head).
// 256 threads: ty=tid/16 (4 rows each), tx=tid%16 (4 cols each).
// Smem (dynamic, 67840 B): QsT[64][68], KtT[64][68], Vt[64][64], PsT[64][65]
// ---------------------------------------------------------------------------
#define QS_PITCH 68
#define PS_PITCH 65
#define ATTN_SMEM ((64 * 68 + 64 * 68 + 64 * 64 + 64 * 65) * 4)

__global__ __launch_bounds__(256, 3)
void attn_kernel()
{
    extern __shared__ float smem[];
    float* QsT = smem;                       // [d][r]  64*68
    float* KtT = QsT + 64 * QS_PITCH;        // [d][c]  64*68
    float* Vt  = KtT + 64 * QS_PITCH;        // [kk][c] 64*64
    float* PsT = Vt + 64 * 64;               // [kk][r] 64*65

    const int qt = blockIdx.x;   // 0..31
    const int h  = blockIdx.y;   // 0..15
    const float* qh = g_q + (size_t)h * SEQ * HDK;
    const float* kh = g_k + (size_t)h * SEQ * HDK;
    const float* vh = g_v + (size_t)h * SEQ * HDK;

    const int tid = threadIdx.x;
    const int ty = tid >> 4, tx = tid & 15;
    const int r0 = qt * 64;

    // Load Q tile transposed: QsT[d][r]
    #pragma unroll
    for (int i = 0; i < 4; i++) {
        int idx = tid + i * 256;             // 0..1023 float4s
        int r = idx >> 4, c4 = (idx & 15) * 4;
        float4 v4 = *(const float4*)&qh[(size_t)(r0 + r) * HDK + c4];
        QsT[(c4 + 0) * QS_PITCH + r] = v4.x;
        QsT[(c4 + 1) * QS_PITCH + r] = v4.y;
        QsT[(c4 + 2) * QS_PITCH + r] = v4.z;
        QsT[(c4 + 3) * QS_PITCH + r] = v4.w;
    }

    float Oacc[4][4];
    float m_i[4], l_i[4];
    #pragma unroll
    for (int i = 0; i < 4; i++) {
        m_i[i] = -INFINITY; l_i[i] = 0.f;
        #pragma unroll
        for (int j = 0; j < 4; j++) Oacc[i][j] = 0.f;
    }

    const float scale = 0.125f;  // 1/sqrt(64)

    for (int j0 = 0; j0 < SEQ; j0 += 64) {
        __syncthreads();  // prev PV reads of Vt / this Q load complete
        // Load K tile transposed (KtT[d][c]) and V tile straight (Vt[kk][c])
        #pragma unroll
        for (int i = 0; i < 4; i++) {
            int idx = tid + i * 256;
            int r = idx >> 4, c4 = (idx & 15) * 4;
            float4 v4 = *(const float4*)&kh[(size_t)(j0 + r) * HDK + c4];
            KtT[(c4 + 0) * QS_PITCH + r] = v4.x;
            KtT[(c4 + 1) * QS_PITCH + r] = v4.y;
            KtT[(c4 + 2) * QS_PITCH + r] = v4.z;
            KtT[(c4 + 3) * QS_PITCH + r] = v4.w;
            float4 w4 = *(const float4*)&vh[(size_t)(j0 + r) * HDK + c4];
            *(float4*)&Vt[r * 64 + c4] = w4;
        }
        __syncthreads();

        // Scores: sc[i][j] = sum_d Q[r0+4ty+i][d] * K[j0+4tx+j][d]
        float sc[4][4];
        #pragma unroll
        for (int i = 0; i < 4; i++)
            #pragma unroll
            for (int j = 0; j < 4; j++) sc[i][j] = 0.f;

        #pragma unroll 8
        for (int d = 0; d < 64; d++) {
            float qf[4], kf[4];
            *(float4*)qf = *(const float4*)&QsT[d * QS_PITCH + ty * 4];
            *(float4*)kf = *(const float4*)&KtT[d * QS_PITCH + tx * 4];
            #pragma unroll
            for (int i = 0; i < 4; i++)
                #pragma unroll
                for (int j = 0; j < 4; j++)
                    sc[i][j] = fmaf(qf[i], kf[j], sc[i][j]);
        }

        // Online softmax update
        float mnew[4], alpha[4], rs[4];
        #pragma unroll
        for (int i = 0; i < 4; i++) {
            float mx = sc[i][0];
            #pragma unroll
            for (int j = 1; j < 4; j++) mx = fmaxf(mx, sc[i][j]);
            mx *= scale;
            #pragma unroll
            for (int off = 1; off < 16; off <<= 1)
                mx = fmaxf(mx, __shfl_xor_sync(0xffffffffu, mx, off));
            mnew[i]  = fmaxf(m_i[i], mx);
            alpha[i] = __expf(m_i[i] - mnew[i]);   // exp(-inf - finite) = 0 first tile
        }
        #pragma unroll
        for (int i = 0; i < 4; i++) {
            rs[i] = 0.f;
            #pragma unroll
            for (int j = 0; j < 4; j++) {
                float p = __expf(sc[i][j] * scale - mnew[i]);
                sc[i][j] = p;
                rs[i] += p;
            }
            #pragma unroll
            for (int off = 1; off < 16; off <<= 1)
                rs[i] += __shfl_xor_sync(0xffffffffu, rs[i], off);
            l_i[i] = l_i[i] * alpha[i] + rs[i];
            m_i[i] = mnew[i];
            #pragma unroll
            for (int j = 0; j < 4; j++) Oacc[i][j] *= alpha[i];
        }

        // Stage P transposed: PsT[key][row]
        #pragma unroll
        for (int i = 0; i < 4; i++)
            #pragma unroll
            for (int j = 0; j < 4; j++)
                PsT[(tx * 4 + j) * PS_PITCH + ty * 4 + i] = sc[i][j];
        __syncthreads();

        // PV: Oacc[i][j] += sum_kk P[r][kk] * V[kk][c]
        #pragma unroll 8
        for (int kk = 0; kk < 64; kk++) {
            float pf[4], vf[4];
            #pragma unroll
            for (int i = 0; i < 4; i++) pf[i] = PsT[kk * PS_PITCH + ty * 4 + i];
            *(float4*)vf = *(const float4*)&Vt[kk * 64 + tx * 4];
            #pragma unroll
            for (int i = 0; i < 4; i++)
                #pragma unroll
                for (int j = 0; j < 4; j++)
                    Oacc[i][j] = fmaf(pf[i], vf[j], Oacc[i][j]);
        }
    }

    // Normalize + write concat[s][h*64 + c]
    #pragma unroll
    for (int i = 0; i < 4; i++) {
        float inv = 1.f / l_i[i];
        int r = r0 + ty * 4 + i;
        #pragma unroll
        for (int j = 0; j < 4; j++)
            g_concat[(size_t)r * DMODEL + h * HDK + tx * 4 + j] = Oacc[i][j] * inv;
    }
}

// ---------------------------------------------------------------------------
extern "C" void kernel_launch(void* const* d_in, const int* in_sizes, int n_in,
                              void* d_out, int out_size)
{
    const float* Q  = (const float*)d_in[0];
    const float* K  = (const float*)d_in[1];
    const float* V  = (const float*)d_in[2];
    const float* Wq = (const float*)d_in[3];
    const float* bq = (const float*)d_in[4];
    const float* Wk = (const float*)d_in[5];
    const float* bk = (const float*)d_in[6];
    const float* Wv = (const float*)d_in[7];
    const float* bv = (const float*)d_in[8];
    const float* Wo = (const float*)d_in[9];
    const float* bo = (const float*)d_in[10];
    float* out = (float*)d_out;

    cudaFuncSetAttribute(attn_kernel,
                         cudaFuncAttributeMaxDynamicSharedMemorySize, ATTN_SMEM);

    dim3 pgrid(SEQ / 128, NH, 3);
    proj_kernel<<<pgrid, 256>>>(Q, K, V, Wq, Wk, Wv, bq, bk, bv);

    dim3 agrid(SEQ / 64, NH);
    attn_kernel<<<agrid, 256, ATTN_SMEM>>>();

    dim3 ogrid(SEQ / 128, DMODEL / 64);
    outproj_kernel<<<ogrid, 256>>>(Wo, bo, out);
}

// round 4
// speedup vs baseline: 2.7766x; 2.7766x over previous
#include <cuda_runtime.h>
#include <cuda_bf16.h>
#include <math.h>
#include <stdint.h>

#define SEQ 2048
#define DMODEL 1024
#define NH 16
#define HDK 64

// ---------------------------------------------------------------------------
// Scratch (__device__ globals: allocation-free contract). All bf16 hi/lo pairs.
// ---------------------------------------------------------------------------
__device__ __nv_bfloat16 g_Xhi[3][SEQ * DMODEL];    // model inputs Q,K,V
__device__ __nv_bfloat16 g_Xlo[3][SEQ * DMODEL];
__device__ __nv_bfloat16 g_Whi[4][DMODEL * DMODEL]; // Wq,Wk,Wv,Wo as [N][K]
__device__ __nv_bfloat16 g_Wlo[4][DMODEL * DMODEL];
__device__ __nv_bfloat16 g_Phi[3][SEQ * DMODEL];    // projected q,k,v [S][h*64+dk]
__device__ __nv_bfloat16 g_Plo[3][SEQ * DMODEL];
__device__ __nv_bfloat16 g_Ohi[SEQ * DMODEL];       // concat (attention out)
__device__ __nv_bfloat16 g_Olo[SEQ * DMODEL];

// ---------------------------------------------------------------------------
// Helpers
// ---------------------------------------------------------------------------
__device__ __forceinline__ uint32_t smem_u32(const void* p) {
    uint32_t a;
    asm("{ .reg .u64 t; cvta.to.shared.u64 t, %1; cvt.u32.u64 %0, t; }" : "=r"(a) : "l"(p));
    return a;
}

#define CP16(dst, src) \
    asm volatile("cp.async.cg.shared.global [%0], [%1], 16;" :: "r"((uint32_t)(dst)), "l"(src) : "memory")
#define CP_COMMIT() asm volatile("cp.async.commit_group;" ::: "memory")
#define CP_WAIT0()  asm volatile("cp.async.wait_group 0;" ::: "memory")
#define CP_WAIT1()  asm volatile("cp.async.wait_group 1;" ::: "memory")

__device__ __forceinline__ void ldsm4(uint32_t* r, uint32_t addr) {
    asm volatile("ldmatrix.sync.aligned.m8n8.x4.shared.b16 {%0,%1,%2,%3}, [%4];"
                 : "=r"(r[0]), "=r"(r[1]), "=r"(r[2]), "=r"(r[3]) : "r"(addr));
}
__device__ __forceinline__ void ldsm4t(uint32_t* r, uint32_t addr) {
    asm volatile("ldmatrix.sync.aligned.m8n8.x4.trans.shared.b16 {%0,%1,%2,%3}, [%4];"
                 : "=r"(r[0]), "=r"(r[1]), "=r"(r[2]), "=r"(r[3]) : "r"(addr));
}
__device__ __forceinline__ void mma16816(float* c, const uint32_t* a, uint32_t b0, uint32_t b1) {
    asm volatile("mma.sync.aligned.m16n8k16.row.col.f32.bf16.bf16.f32 "
                 "{%0,%1,%2,%3}, {%4,%5,%6,%7}, {%8,%9}, {%0,%1,%2,%3};"
                 : "+f"(c[0]), "+f"(c[1]), "+f"(c[2]), "+f"(c[3])
                 : "r"(a[0]), "r"(a[1]), "r"(a[2]), "r"(a[3]), "r"(b0), "r"(b1));
}

__device__ __forceinline__ uint32_t packbf(float a, float b) {
    __nv_bfloat162 t = __floats2bfloat162_rn(a, b);
    return *reinterpret_cast<uint32_t*>(&t);
}
__device__ __forceinline__ void split2(float x, float& hf, float& lf) {
    hf = __bfloat162float(__float2bfloat16(x));
    lf = x - hf;
}
__device__ __forceinline__ void hilo_pack(float x, float y, uint32_t& ph, uint32_t& pl) {
    float hx, lx, hy, ly;
    split2(x, hx, lx); split2(y, hy, ly);
    ph = packbf(hx, hy); pl = packbf(lx, ly);
}

// smem tile row pitch: 64 bf16 data (128B) + 16B pad = 144B. ldmatrix-conflict-free.
#define TP 144

// ldmatrix address generators (tileBase = smem u32 of tile start)
// A (row-major m16k16): regs a0..a3 = (r+gid,klo),(r+8+gid,klo),(r,khi),(r+8,khi)
__device__ __forceinline__ uint32_t a_addr(uint32_t tb, int r0, int kb, int lane) {
    int sub = lane >> 3, ll = lane & 7;
    return tb + (uint32_t)(r0 + ((sub & 1) << 3) + ll) * TP + kb + ((sub >> 1) << 4);
}
// B from [n][k] row-major (non-trans): regs = b0(nt0),b1(nt0),b0(nt1),b1(nt1)
__device__ __forceinline__ uint32_t b_addr(uint32_t tb, int n0, int kb, int lane) {
    int sub = lane >> 3, ll = lane & 7;
    return tb + (uint32_t)(n0 + ((sub >> 1) << 3) + ll) * TP + kb + ((sub & 1) << 4);
}
// B from [k][n] row-major (trans): regs = b0(nt0),b1(nt0),b0(nt1),b1(nt1)
__device__ __forceinline__ uint32_t v_addr(uint32_t tb, int k0, int nb, int lane) {
    int sub = lane >> 3, ll = lane & 7;
    return tb + (uint32_t)(k0 + ((sub & 1) << 3) + ll) * TP + nb + ((sub >> 1) << 4);
}

// ---------------------------------------------------------------------------
// Conversion kernels
// ---------------------------------------------------------------------------
__global__ void conv_in_kernel(const float* __restrict__ Q, const float* __restrict__ K,
                               const float* __restrict__ V)
{
    int z = blockIdx.y;
    const float* src = (z == 0) ? Q : (z == 1) ? K : V;
    size_t i = ((size_t)blockIdx.x * 256 + threadIdx.x) * 4;
    float4 v = *(const float4*)(src + i);
    float h0,l0,h1,l1,h2,l2,h3,l3;
    split2(v.x,h0,l0); split2(v.y,h1,l1); split2(v.z,h2,l2); split2(v.w,h3,l3);
    *(uint32_t*)&g_Xhi[z][i]   = packbf(h0,h1);
    *(uint32_t*)&g_Xhi[z][i+2] = packbf(h2,h3);
    *(uint32_t*)&g_Xlo[z][i]   = packbf(l0,l1);
    *(uint32_t*)&g_Xlo[z][i+2] = packbf(l2,l3);
}

// Transpose+split: src [R][C] fp32 -> dst [C][R] hi/lo bf16 (batched on z)
__global__ void conv_w_kernel(const float* __restrict__ src,
                              __nv_bfloat16* __restrict__ dhi,
                              __nv_bfloat16* __restrict__ dlo,
                              int R, int C)
{
    src += (size_t)blockIdx.z * R * C;
    dhi += (size_t)blockIdx.z * R * C;
    dlo += (size_t)blockIdx.z * R * C;
    __shared__ float t[64][65];
    int r0 = blockIdx.x * 64, c0 = blockIdx.y * 64;
    int tid = threadIdx.x;
    #pragma unroll
    for (int i = 0; i < 16; i++) {
        int idx = tid + i * 256;
        int rr = idx >> 6, cc = idx & 63;
        t[cc][rr] = src[(size_t)(r0 + rr) * C + c0 + cc];
    }
    __syncthreads();
    #pragma unroll
    for (int i = 0; i < 16; i++) {
        int idx = tid + i * 256;
        int rr = idx >> 6, cc = idx & 63;
        float h, l;
        split2(t[rr][cc], h, l);
        dhi[(size_t)(c0 + rr) * R + r0 + cc] = __float2bfloat16(h);
        dlo[(size_t)(c0 + rr) * R + r0 + cc] = __float2bfloat16(l);
    }
}

// ---------------------------------------------------------------------------
// HMMA bf16x3 GEMM: C[2048x128N-tiles] = A[S][1024] * B^T ([N][K]) + bias
// CTA 128x128, 8 warps (warp 32x64), K-chunk 64, double-buffered cp.async.
// smem: 2 stages x 4 matrices x (128 rows x 144B) = 147456 B
// ---------------------------------------------------------------------------
#define G_MAT   18432
#define G_STAGE (4 * G_MAT)
#define G_SMEM  (2 * G_STAGE)

__device__ __forceinline__ void g_load_chunk(
    uint32_t st,
    const __nv_bfloat16* __restrict__ Ahi, const __nv_bfloat16* __restrict__ Alo,
    const __nv_bfloat16* __restrict__ Bhi, const __nv_bfloat16* __restrict__ Blo,
    int m0, int n0, int k0, int tid)
{
    #pragma unroll
    for (int i = 0; i < 4; i++) {
        int idx = tid + i * 256;
        int r = idx >> 3, c = idx & 7;
        uint32_t so = (uint32_t)r * TP + c * 16;
        size_t ga = (size_t)(m0 + r) * DMODEL + k0 + c * 8;
        size_t gb = (size_t)(n0 + r) * DMODEL + k0 + c * 8;
        CP16(st + so,             Ahi + ga);
        CP16(st + G_MAT + so,     Alo + ga);
        CP16(st + 2 * G_MAT + so, Bhi + gb);
        CP16(st + 3 * G_MAT + so, Blo + gb);
    }
    CP_COMMIT();
}

__device__ __forceinline__ void g_compute_chunk(uint32_t st, int lane, int wr, int wc,
                                                float C[2][8][4])
{
    #pragma unroll
    for (int ks = 0; ks < 4; ks++) {
        int kb = ks * 32;
        uint32_t ah[2][4], al[2][4];
        #pragma unroll
        for (int mt = 0; mt < 2; mt++) {
            ldsm4(ah[mt], a_addr(st,         wr * 32 + mt * 16, kb, lane));
            ldsm4(al[mt], a_addr(st + G_MAT, wr * 32 + mt * 16, kb, lane));
        }
        #pragma unroll
        for (int nt2 = 0; nt2 < 4; nt2++) {
            uint32_t bh[4], bl[4];
            ldsm4(bh, b_addr(st + 2 * G_MAT, wc * 64 + nt2 * 16, kb, lane));
            ldsm4(bl, b_addr(st + 3 * G_MAT, wc * 64 + nt2 * 16, kb, lane));
            #pragma unroll
            for (int mt = 0; mt < 2; mt++) {
                mma16816(C[mt][nt2*2],   ah[mt], bh[0], bh[1]);
                mma16816(C[mt][nt2*2],   ah[mt], bl[0], bl[1]);
                mma16816(C[mt][nt2*2],   al[mt], bh[0], bh[1]);
                mma16816(C[mt][nt2*2+1], ah[mt], bh[2], bh[3]);
                mma16816(C[mt][nt2*2+1], ah[mt], bl[2], bl[3]);
                mma16816(C[mt][nt2*2+1], al[mt], bh[2], bh[3]);
            }
        }
    }
}

// mode 0: write bf16 hi/lo (projections); mode 1: write fp32 (final output)
__device__ __forceinline__ void gemm_body(
    const __nv_bfloat16* __restrict__ Ahi, const __nv_bfloat16* __restrict__ Alo,
    const __nv_bfloat16* __restrict__ Bhi, const __nv_bfloat16* __restrict__ Blo,
    const float* __restrict__ bias,
    __nv_bfloat16* __restrict__ Chi, __nv_bfloat16* __restrict__ Clo,
    float* __restrict__ Cf, int mode)
{
    extern __shared__ __align__(128) char smem[];
    uint32_t sb = smem_u32(smem);
    const int tid = threadIdx.x;
    const int wid = tid >> 5, lane = tid & 31;
    const int wr = wid & 3, wc = wid >> 2;
    const int m0 = blockIdx.x * 128, n0 = blockIdx.y * 128;

    float C[2][8][4];
    #pragma unroll
    for (int a = 0; a < 2; a++)
        #pragma unroll
        for (int b = 0; b < 8; b++)
            #pragma unroll
            for (int c = 0; c < 4; c++) C[a][b][c] = 0.f;

    g_load_chunk(sb, Ahi, Alo, Bhi, Blo, m0, n0, 0, tid);

    for (int i = 0; i < 16; i++) {
        uint32_t stCur = sb + (i & 1) * G_STAGE;
        if (i + 1 < 16)
            g_load_chunk(sb + ((i + 1) & 1) * G_STAGE, Ahi, Alo, Bhi, Blo,
                         m0, n0, (i + 1) * 64, tid);
        if (i + 1 < 16) { CP_WAIT1(); } else { CP_WAIT0(); }
        __syncthreads();
        g_compute_chunk(stCur, lane, wr, wc, C);
        __syncthreads();
    }

    // epilogue
    const int gid = lane >> 2, tig = lane & 3;
    #pragma unroll
    for (int mt = 0; mt < 2; mt++) {
        int row0 = m0 + wr * 32 + mt * 16 + gid;
        #pragma unroll
        for (int nt = 0; nt < 8; nt++) {
            int col = n0 + wc * 64 + nt * 8 + tig * 2;
            float b0 = bias[col], b1 = bias[col + 1];
            float v00 = C[mt][nt][0] + b0, v01 = C[mt][nt][1] + b1;
            float v10 = C[mt][nt][2] + b0, v11 = C[mt][nt][3] + b1;
            if (mode == 0) {
                uint32_t ph, pl;
                hilo_pack(v00, v01, ph, pl);
                *(uint32_t*)&Chi[(size_t)row0 * DMODEL + col] = ph;
                *(uint32_t*)&Clo[(size_t)row0 * DMODEL + col] = pl;
                hilo_pack(v10, v11, ph, pl);
                *(uint32_t*)&Chi[(size_t)(row0 + 8) * DMODEL + col] = ph;
                *(uint32_t*)&Clo[(size_t)(row0 + 8) * DMODEL + col] = pl;
            } else {
                *(float2*)&Cf[(size_t)row0 * DMODEL + col] = make_float2(v00, v01);
                *(float2*)&Cf[(size_t)(row0 + 8) * DMODEL + col] = make_float2(v10, v11);
            }
        }
    }
}

__global__ __launch_bounds__(256, 1)
void proj_gemm_kernel(const float* __restrict__ bq, const float* __restrict__ bk,
                      const float* __restrict__ bv)
{
    int z = blockIdx.z;
    const float* bias = (z == 0) ? bq : (z == 1) ? bk : bv;
    gemm_body(g_Xhi[z], g_Xlo[z], g_Whi[z], g_Wlo[z], bias,
              g_Phi[z], g_Plo[z], nullptr, 0);
}

__global__ __launch_bounds__(256, 1)
void out_gemm_kernel(const float* __restrict__ bo, float* __restrict__ out)
{
    gemm_body(g_Ohi, g_Olo, g_Whi[3], g_Wlo[3], bo, nullptr, nullptr, out, 1);
}

// ---------------------------------------------------------------------------
// Flash attention, HMMA bf16x3. CTA = 64 q-rows x 1 head, 4 warps (m16n64 each).
// smem: Qhi,Qlo,Khi,Klo,Vhi,Vlo tiles 64x144B = 55296 B
// ---------------------------------------------------------------------------
#define AT_TILE (64 * TP)
#define A_QHI 0
#define A_QLO (1 * AT_TILE)
#define A_KHI (2 * AT_TILE)
#define A_KLO (3 * AT_TILE)
#define A_VHI (4 * AT_TILE)
#define A_VLO (5 * AT_TILE)
#define A_SMEM (6 * AT_TILE)

__global__ __launch_bounds__(128, 2)
void attn_kernel()
{
    extern __shared__ __align__(128) char smem[];
    uint32_t sb = smem_u32(smem);
    const int tid = threadIdx.x;
    const int wid = tid >> 5, lane = tid & 31;
    const int gid = lane >> 2, tig = lane & 3;
    const int qt = blockIdx.x, h = blockIdx.y;
    const int r0 = qt * 64;
    const int colBase = h * HDK;

    const __nv_bfloat16* qhi = g_Phi[0]; const __nv_bfloat16* qlo = g_Plo[0];
    const __nv_bfloat16* khi = g_Phi[1]; const __nv_bfloat16* klo = g_Plo[1];
    const __nv_bfloat16* vhi = g_Phi[2]; const __nv_bfloat16* vlo = g_Plo[2];

    // Load Q tiles (hi/lo): 64 rows x 8 chunks x 2 mats = 1024 CP16 / 128 thr
    #pragma unroll
    for (int i = 0; i < 4; i++) {
        int idx = tid + i * 128;
        int r = idx >> 3, c = idx & 7;
        uint32_t so = (uint32_t)r * TP + c * 16;
        size_t g = (size_t)(r0 + r) * DMODEL + colBase + c * 8;
        CP16(sb + A_QHI + so, qhi + g);
        CP16(sb + A_QLO + so, qlo + g);
    }
    CP_COMMIT(); CP_WAIT0();
    __syncthreads();

    // Q fragments in registers (per warp: rows 16*wid..16*wid+15, all 64 d)
    uint32_t qfh[4][4], qfl[4][4];
    #pragma unroll
    for (int ks = 0; ks < 4; ks++) {
        ldsm4(qfh[ks], a_addr(sb + A_QHI, wid * 16, ks * 32, lane));
        ldsm4(qfl[ks], a_addr(sb + A_QLO, wid * 16, ks * 32, lane));
    }

    float O[8][4];
    #pragma unroll
    for (int a = 0; a < 8; a++)
        #pragma unroll
        for (int b = 0; b < 4; b++) O[a][b] = 0.f;
    float m0 = -INFINITY, m1 = -INFINITY, l0 = 0.f, l1 = 0.f;
    const float scale = 0.125f;

    for (int jt = 0; jt < 32; jt++) {
        int j0 = jt * 64;
        __syncthreads();   // previous PV done reading K/V
        #pragma unroll
        for (int i = 0; i < 4; i++) {
            int idx = tid + i * 128;
            int r = idx >> 3, c = idx & 7;
            uint32_t so = (uint32_t)r * TP + c * 16;
            size_t g = (size_t)(j0 + r) * DMODEL + colBase + c * 8;
            CP16(sb + A_KHI + so, khi + g);
            CP16(sb + A_KLO + so, klo + g);
            CP16(sb + A_VHI + so, vhi + g);
            CP16(sb + A_VLO + so, vlo + g);
        }
        CP_COMMIT(); CP_WAIT0();
        __syncthreads();

        // ---- scores: sc[nt] covers keys j0+8nt..+7 ----
        float sc[8][4];
        #pragma unroll
        for (int a = 0; a < 8; a++)
            #pragma unroll
            for (int b = 0; b < 4; b++) sc[a][b] = 0.f;

        #pragma unroll
        for (int ks = 0; ks < 4; ks++) {
            int kb = ks * 32;
            #pragma unroll
            for (int nt2 = 0; nt2 < 4; nt2++) {
                uint32_t bh[4], bl[4];
                ldsm4(bh, b_addr(sb + A_KHI, nt2 * 16, kb, lane));
                ldsm4(bl, b_addr(sb + A_KLO, nt2 * 16, kb, lane));
                mma16816(sc[nt2*2],   qfh[ks], bh[0], bh[1]);
                mma16816(sc[nt2*2],   qfh[ks], bl[0], bl[1]);
                mma16816(sc[nt2*2],   qfl[ks], bh[0], bh[1]);
                mma16816(sc[nt2*2+1], qfh[ks], bh[2], bh[3]);
                mma16816(sc[nt2*2+1], qfh[ks], bl[2], bl[3]);
                mma16816(sc[nt2*2+1], qfl[ks], bh[2], bh[3]);
            }
        }

        // ---- online softmax (rows: gid and gid+8 within warp's m16) ----
        float mx0 = -INFINITY, mx1 = -INFINITY;
        #pragma unroll
        for (int nt = 0; nt < 8; nt++) {
            mx0 = fmaxf(mx0, fmaxf(sc[nt][0], sc[nt][1]));
            mx1 = fmaxf(mx1, fmaxf(sc[nt][2], sc[nt][3]));
        }
        mx0 *= scale; mx1 *= scale;
        mx0 = fmaxf(mx0, __shfl_xor_sync(0xffffffffu, mx0, 1));
        mx0 = fmaxf(mx0, __shfl_xor_sync(0xffffffffu, mx0, 2));
        mx1 = fmaxf(mx1, __shfl_xor_sync(0xffffffffu, mx1, 1));
        mx1 = fmaxf(mx1, __shfl_xor_sync(0xffffffffu, mx1, 2));
        float mn0 = fmaxf(m0, mx0), mn1 = fmaxf(m1, mx1);
        float al0 = __expf(m0 - mn0), al1 = __expf(m1 - mn1);

        float s0 = 0.f, s1 = 0.f;
        #pragma unroll
        for (int nt = 0; nt < 8; nt++) {
            float p0 = __expf(sc[nt][0] * scale - mn0);
            float p1 = __expf(sc[nt][1] * scale - mn0);
            float p2 = __expf(sc[nt][2] * scale - mn1);
            float p3 = __expf(sc[nt][3] * scale - mn1);
            sc[nt][0] = p0; sc[nt][1] = p1; sc[nt][2] = p2; sc[nt][3] = p3;
            s0 += p0 + p1; s1 += p2 + p3;
        }
        s0 += __shfl_xor_sync(0xffffffffu, s0, 1);
        s0 += __shfl_xor_sync(0xffffffffu, s0, 2);
        s1 += __shfl_xor_sync(0xffffffffu, s1, 1);
        s1 += __shfl_xor_sync(0xffffffffu, s1, 2);
        l0 = l0 * al0 + s0; l1 = l1 * al1 + s1;
        m0 = mn0; m1 = mn1;
        #pragma unroll
        for (int nt = 0; nt < 8; nt++) {
            O[nt][0] *= al0; O[nt][1] *= al0;
            O[nt][2] *= al1; O[nt][3] *= al1;
        }

        // ---- PV: O[m16][d64] += P[m16][key64] * V[key64][d64] ----
        #pragma unroll
        for (int kt = 0; kt < 4; kt++) {
            // P A-frags from score tiles 2kt, 2kt+1 (in registers)
            uint32_t ph[4], pl[4];
            hilo_pack(sc[2*kt][0],   sc[2*kt][1],   ph[0], pl[0]);
            hilo_pack(sc[2*kt][2],   sc[2*kt][3],   ph[1], pl[1]);
            hilo_pack(sc[2*kt+1][0], sc[2*kt+1][1], ph[2], pl[2]);
            hilo_pack(sc[2*kt+1][2], sc[2*kt+1][3], ph[3], pl[3]);
            #pragma unroll
            for (int nt2 = 0; nt2 < 4; nt2++) {
                uint32_t vh[4], vl[4];
                ldsm4t(vh, v_addr(sb + A_VHI, kt * 16, nt2 * 32, lane));
                ldsm4t(vl, v_addr(sb + A_VLO, kt * 16, nt2 * 32, lane));
                mma16816(O[nt2*2],   ph, vh[0], vh[1]);
                mma16816(O[nt2*2],   ph, vl[0], vl[1]);
                mma16816(O[nt2*2],   pl, vh[0], vh[1]);
                mma16816(O[nt2*2+1], ph, vh[2], vh[3]);
                mma16816(O[nt2*2+1], ph, vl[2], vl[3]);
                mma16816(O[nt2*2+1], pl, vh[2], vh[3]);
            }
        }
    }

    // ---- epilogue: normalize, split hi/lo, write concat ----
    float inv0 = 1.f / l0, inv1 = 1.f / l1;
    int rowA = r0 + wid * 16 + gid;
    #pragma unroll
    for (int nt = 0; nt < 8; nt++) {
        int col = colBase + nt * 8 + tig * 2;
        uint32_t ph, pl;
        hilo_pack(O[nt][0] * inv0, O[nt][1] * inv0, ph, pl);
        *(uint32_t*)&g_Ohi[(size_t)rowA * DMODEL + col] = ph;
        *(uint32_t*)&g_Olo[(size_t)rowA * DMODEL + col] = pl;
        hilo_pack(O[nt][2] * inv1, O[nt][3] * inv1, ph, pl);
        *(uint32_t*)&g_Ohi[(size_t)(rowA + 8) * DMODEL + col] = ph;
        *(uint32_t*)&g_Olo[(size_t)(rowA + 8) * DMODEL + col] = pl;
    }
}

// ---------------------------------------------------------------------------
extern "C" void kernel_launch(void* const* d_in, const int* in_sizes, int n_in,
                              void* d_out, int out_size)
{
    const float* Q  = (const float*)d_in[0];
    const float* K  = (const float*)d_in[1];
    const float* V  = (const float*)d_in[2];
    const float* Wq = (const float*)d_in[3];
    const float* bq = (const float*)d_in[4];
    const float* Wk = (const float*)d_in[5];
    const float* bk = (const float*)d_in[6];
    const float* Wv = (const float*)d_in[7];
    const float* bv = (const float*)d_in[8];
    const float* Wo = (const float*)d_in[9];
    const float* bo = (const float*)d_in[10];
    float* out = (float*)d_out;

    cudaFuncSetAttribute(proj_gemm_kernel, cudaFuncAttributeMaxDynamicSharedMemorySize, G_SMEM);
    cudaFuncSetAttribute(out_gemm_kernel,  cudaFuncAttributeMaxDynamicSharedMemorySize, G_SMEM);
    cudaFuncSetAttribute(attn_kernel,      cudaFuncAttributeMaxDynamicSharedMemorySize, A_SMEM);

    __nv_bfloat16 *whi, *wlo;
    cudaGetSymbolAddress((void**)&whi, g_Whi);
    cudaGetSymbolAddress((void**)&wlo, g_Wlo);

    conv_in_kernel<<<dim3(SEQ * DMODEL / 1024, 3), 256>>>(Q, K, V);
    conv_w_kernel<<<dim3(16, 1, 16), 256>>>(Wq, whi + 0u * DMODEL * DMODEL, wlo + 0u * DMODEL * DMODEL, 1024, 64);
    conv_w_kernel<<<dim3(16, 1, 16), 256>>>(Wk, whi + 1u * DMODEL * DMODEL, wlo + 1u * DMODEL * DMODEL, 1024, 64);
    conv_w_kernel<<<dim3(16, 1, 16), 256>>>(Wv, whi + 2u * DMODEL * DMODEL, wlo + 2u * DMODEL * DMODEL, 1024, 64);
    conv_w_kernel<<<dim3(16, 16, 1), 256>>>(Wo, whi + 3u * DMODEL * DMODEL, wlo + 3u * DMODEL * DMODEL, 1024, 1024);

    proj_gemm_kernel<<<dim3(16, 8, 3), 256, G_SMEM>>>(bq, bk, bv);
    attn_kernel<<<dim3(SEQ / 64, NH), 128, A_SMEM>>>();
    out_gemm_kernel<<<dim3(16, 8), 256, G_SMEM>>>(bo, out);
}

// round 7
// speedup vs baseline: 2.8699x; 1.0336x over previous
#include <cuda_runtime.h>
#include <cuda_bf16.h>
#include <math.h>
#include <stdint.h>

#define SEQ 2048
#define DMODEL 1024
#define NH 16
#define HDK 64

// ---------------------------------------------------------------------------
// Scratch (__device__ globals: allocation-free contract). All bf16 hi/lo pairs.
// ---------------------------------------------------------------------------
__device__ __nv_bfloat16 g_Xhi[3][SEQ * DMODEL];    // model inputs Q,K,V
__device__ __nv_bfloat16 g_Xlo[3][SEQ * DMODEL];
__device__ __nv_bfloat16 g_Whi[4][DMODEL * DMODEL]; // Wq,Wk,Wv,Wo as [N][K]
__device__ __nv_bfloat16 g_Wlo[4][DMODEL * DMODEL];
__device__ __nv_bfloat16 g_Phi[3][SEQ * DMODEL];    // projected q,k,v [S][h*64+dk]
__device__ __nv_bfloat16 g_Plo[3][SEQ * DMODEL];
__device__ __nv_bfloat16 g_Ohi[SEQ * DMODEL];       // concat (attention out)
__device__ __nv_bfloat16 g_Olo[SEQ * DMODEL];

// ---------------------------------------------------------------------------
// Helpers
// ---------------------------------------------------------------------------
__device__ __forceinline__ uint32_t smem_u32(const void* p) {
    uint32_t a;
    asm("{ .reg .u64 t; cvta.to.shared.u64 t, %1; cvt.u32.u64 %0, t; }" : "=r"(a) : "l"(p));
    return a;
}

#define CP16(dst, src) \
    asm volatile("cp.async.cg.shared.global [%0], [%1], 16;" :: "r"((uint32_t)(dst)), "l"(src) : "memory")
#define CP_COMMIT() asm volatile("cp.async.commit_group;" ::: "memory")
#define CP_WAIT0()  asm volatile("cp.async.wait_group 0;" ::: "memory")
#define CP_WAIT1()  asm volatile("cp.async.wait_group 1;" ::: "memory")

__device__ __forceinline__ void ldsm4(uint32_t* r, uint32_t addr) {
    asm volatile("ldmatrix.sync.aligned.m8n8.x4.shared.b16 {%0,%1,%2,%3}, [%4];"
                 : "=r"(r[0]), "=r"(r[1]), "=r"(r[2]), "=r"(r[3]) : "r"(addr));
}
__device__ __forceinline__ void ldsm4t(uint32_t* r, uint32_t addr) {
    asm volatile("ldmatrix.sync.aligned.m8n8.x4.trans.shared.b16 {%0,%1,%2,%3}, [%4];"
                 : "=r"(r[0]), "=r"(r[1]), "=r"(r[2]), "=r"(r[3]) : "r"(addr));
}
__device__ __forceinline__ void mma16816(float* c, const uint32_t* a, uint32_t b0, uint32_t b1) {
    asm volatile("mma.sync.aligned.m16n8k16.row.col.f32.bf16.bf16.f32 "
                 "{%0,%1,%2,%3}, {%4,%5,%6,%7}, {%8,%9}, {%0,%1,%2,%3};"
                 : "+f"(c[0]), "+f"(c[1]), "+f"(c[2]), "+f"(c[3])
                 : "r"(a[0]), "r"(a[1]), "r"(a[2]), "r"(a[3]), "r"(b0), "r"(b1));
}

__device__ __forceinline__ uint32_t packbf(float a, float b) {
    __nv_bfloat162 t = __floats2bfloat162_rn(a, b);
    return *reinterpret_cast<uint32_t*>(&t);
}
__device__ __forceinline__ void split2(float x, float& hf, float& lf) {
    hf = __bfloat162float(__float2bfloat16(x));
    lf = x - hf;
}
__device__ __forceinline__ void hilo_pack(float x, float y, uint32_t& ph, uint32_t& pl) {
    float hx, lx, hy, ly;
    split2(x, hx, lx); split2(y, hy, ly);
    ph = packbf(hx, hy); pl = packbf(lx, ly);
}

// ldmatrix address generators, parametric row pitch P (bytes).
// A (row-major m16k16)
__device__ __forceinline__ uint32_t a_addr(uint32_t tb, int r0, int kb, int lane, int P) {
    int sub = lane >> 3, ll = lane & 7;
    return tb + (uint32_t)(r0 + ((sub & 1) << 3) + ll) * P + kb + ((sub >> 1) << 4);
}
// B from [n][k] row-major (non-trans)
__device__ __forceinline__ uint32_t b_addr(uint32_t tb, int n0, int kb, int lane, int P) {
    int sub = lane >> 3, ll = lane & 7;
    return tb + (uint32_t)(n0 + ((sub >> 1) << 3) + ll) * P + kb + ((sub & 1) << 4);
}
// B from [k][n] row-major (trans)
__device__ __forceinline__ uint32_t v_addr(uint32_t tb, int k0, int nb, int lane, int P) {
    int sub = lane >> 3, ll = lane & 7;
    return tb + (uint32_t)(k0 + ((sub & 1) << 3) + ll) * P + nb + ((sub >> 1) << 4);
}

// ---------------------------------------------------------------------------
// Conversion kernels
// ---------------------------------------------------------------------------
__global__ void conv_in_kernel(const float* __restrict__ Q, const float* __restrict__ K,
                               const float* __restrict__ V)
{
    int z = blockIdx.y;
    const float* src = (z == 0) ? Q : (z == 1) ? K : V;
    size_t i = ((size_t)blockIdx.x * 256 + threadIdx.x) * 4;
    float4 v = *(const float4*)(src + i);
    float h0,l0,h1,l1,h2,l2,h3,l3;
    split2(v.x,h0,l0); split2(v.y,h1,l1); split2(v.z,h2,l2); split2(v.w,h3,l3);
    *(uint32_t*)&g_Xhi[z][i]   = packbf(h0,h1);
    *(uint32_t*)&g_Xhi[z][i+2] = packbf(h2,h3);
    *(uint32_t*)&g_Xlo[z][i]   = packbf(l0,l1);
    *(uint32_t*)&g_Xlo[z][i+2] = packbf(l2,l3);
}

// Transpose+split: src [R][C] fp32 -> dst [C][R] hi/lo bf16
__device__ __forceinline__ void conv_w_body(const float* __restrict__ src,
                                            __nv_bfloat16* __restrict__ dhi,
                                            __nv_bfloat16* __restrict__ dlo,
                                            int R, int C, int bx, int by)
{
    __shared__ float t[64][65];
    int r0 = bx * 64, c0 = by * 64;
    int tid = threadIdx.x;
    #pragma unroll
    for (int i = 0; i < 16; i++) {
        int idx = tid + i * 256;
        int rr = idx >> 6, cc = idx & 63;
        t[cc][rr] = src[(size_t)(r0 + rr) * C + c0 + cc];
    }
    __syncthreads();
    #pragma unroll
    for (int i = 0; i < 16; i++) {
        int idx = tid + i * 256;
        int rr = idx >> 6, cc = idx & 63;
        float h, l;
        split2(t[rr][cc], h, l);
        dhi[(size_t)(c0 + rr) * R + r0 + cc] = __float2bfloat16(h);
        dlo[(size_t)(c0 + rr) * R + r0 + cc] = __float2bfloat16(l);
    }
}

// Wq,Wk,Wv in one launch: grid (16, 1, 48); z/16 selects matrix
__global__ void conv_w3_kernel(const float* __restrict__ Wq, const float* __restrict__ Wk,
                               const float* __restrict__ Wv)
{
    int which = blockIdx.z >> 4, zz = blockIdx.z & 15;
    const float* src = (which == 0) ? Wq : (which == 1) ? Wk : Wv;
    conv_w_body(src + (size_t)zz * DMODEL * HDK,
                &g_Whi[which][(size_t)zz * DMODEL * HDK],
                &g_Wlo[which][(size_t)zz * DMODEL * HDK],
                1024, 64, blockIdx.x, 0);
}

__global__ void conv_wo_kernel(const float* __restrict__ Wo)
{
    conv_w_body(Wo, g_Whi[3], g_Wlo[3], 1024, 1024, blockIdx.x, blockIdx.y);
}

// ---------------------------------------------------------------------------
// HMMA bf16x3 GEMM: C = A[S][1024] * B^T ([N][K]) + bias. CTA 128x128, 8 warps,
// K-chunk 32, double-buffered, 80B smem pitch -> 2 CTAs/SM.
// ---------------------------------------------------------------------------
#define TPG 80
#define G_MAT   (128 * TPG)
#define G_STAGE (4 * G_MAT)
#define G_SMEM  (2 * G_STAGE)
#define G_NCHUNK 32

__device__ __forceinline__ void g_load_chunk(
    uint32_t st,
    const __nv_bfloat16* __restrict__ Ahi, const __nv_bfloat16* __restrict__ Alo,
    const __nv_bfloat16* __restrict__ Bhi, const __nv_bfloat16* __restrict__ Blo,
    int m0, int n0, int k0, int tid)
{
    const __nv_bfloat16* srcs[4] = {Ahi, Alo, Bhi, Blo};
    #pragma unroll
    for (int i = 0; i < 8; i++) {
        int mat = i >> 1;
        int j = ((i & 1) << 8) + tid;        // 0..511
        int r = j >> 2, c = j & 3;
        uint32_t so = (uint32_t)r * TPG + c * 16;
        int row = ((mat < 2) ? m0 : n0) + r;
        CP16(st + mat * G_MAT + so, srcs[mat] + (size_t)row * DMODEL + k0 + c * 8);
    }
    CP_COMMIT();
}

__device__ __forceinline__ void g_compute_chunk(uint32_t st, int lane, int wr, int wc,
                                                float C[2][8][4])
{
    #pragma unroll
    for (int ks = 0; ks < 2; ks++) {
        int kb = ks * 32;
        uint32_t ah[2][4], al[2][4];
        #pragma unroll
        for (int mt = 0; mt < 2; mt++) {
            ldsm4(ah[mt], a_addr(st,         wr * 32 + mt * 16, kb, lane, TPG));
            ldsm4(al[mt], a_addr(st + G_MAT, wr * 32 + mt * 16, kb, lane, TPG));
        }
        #pragma unroll
        for (int nt2 = 0; nt2 < 4; nt2++) {
            uint32_t bh[4], bl[4];
            ldsm4(bh, b_addr(st + 2 * G_MAT, wc * 64 + nt2 * 16, kb, lane, TPG));
            ldsm4(bl, b_addr(st + 3 * G_MAT, wc * 64 + nt2 * 16, kb, lane, TPG));
            #pragma unroll
            for (int mt = 0; mt < 2; mt++) {
                mma16816(C[mt][nt2*2],   ah[mt], bh[0], bh[1]);
                mma16816(C[mt][nt2*2],   ah[mt], bl[0], bl[1]);
                mma16816(C[mt][nt2*2],   al[mt], bh[0], bh[1]);
                mma16816(C[mt][nt2*2+1], ah[mt], bh[2], bh[3]);
                mma16816(C[mt][nt2*2+1], ah[mt], bl[2], bl[3]);
                mma16816(C[mt][nt2*2+1], al[mt], bh[2], bh[3]);
            }
        }
    }
}

__device__ __forceinline__ void gemm_body(
    const __nv_bfloat16* __restrict__ Ahi, const __nv_bfloat16* __restrict__ Alo,
    const __nv_bfloat16* __restrict__ Bhi, const __nv_bfloat16* __restrict__ Blo,
    const float* __restrict__ bias,
    __nv_bfloat16* __restrict__ Chi, __nv_bfloat16* __restrict__ Clo,
    float* __restrict__ Cf, int mode)
{
    extern __shared__ __align__(128) char smem[];
    uint32_t sb = smem_u32(smem);
    const int tid = threadIdx.x;
    const int wid = tid >> 5, lane = tid & 31;
    const int wr = wid & 3, wc = wid >> 2;
    const int m0 = blockIdx.x * 128, n0 = blockIdx.y * 128;

    float C[2][8][4];
    #pragma unroll
    for (int a = 0; a < 2; a++)
        #pragma unroll
        for (int b = 0; b < 8; b++)
            #pragma unroll
            for (int c = 0; c < 4; c++) C[a][b][c] = 0.f;

    g_load_chunk(sb, Ahi, Alo, Bhi, Blo, m0, n0, 0, tid);

    for (int i = 0; i < G_NCHUNK; i++) {
        uint32_t stCur = sb + (i & 1) * G_STAGE;
        if (i + 1 < G_NCHUNK) {
            g_load_chunk(sb + ((i + 1) & 1) * G_STAGE, Ahi, Alo, Bhi, Blo,
                         m0, n0, (i + 1) * 32, tid);
            CP_WAIT1();
        } else {
            CP_WAIT0();
        }
        __syncthreads();
        g_compute_chunk(stCur, lane, wr, wc, C);
        __syncthreads();
    }

    const int gid = lane >> 2, tig = lane & 3;
    #pragma unroll
    for (int mt = 0; mt < 2; mt++) {
        int row0 = m0 + wr * 32 + mt * 16 + gid;
        #pragma unroll
        for (int nt = 0; nt < 8; nt++) {
            int col = n0 + wc * 64 + nt * 8 + tig * 2;
            float b0 = bias[col], b1 = bias[col + 1];
            float v00 = C[mt][nt][0] + b0, v01 = C[mt][nt][1] + b1;
            float v10 = C[mt][nt][2] + b0, v11 = C[mt][nt][3] + b1;
            if (mode == 0) {
                uint32_t ph, pl;
                hilo_pack(v00, v01, ph, pl);
                *(uint32_t*)&Chi[(size_t)row0 * DMODEL + col] = ph;
                *(uint32_t*)&Clo[(size_t)row0 * DMODEL + col] = pl;
                hilo_pack(v10, v11, ph, pl);
                *(uint32_t*)&Chi[(size_t)(row0 + 8) * DMODEL + col] = ph;
                *(uint32_t*)&Clo[(size_t)(row0 + 8) * DMODEL + col] = pl;
            } else {
                *(float2*)&Cf[(size_t)row0 * DMODEL + col] = make_float2(v00, v01);
                *(float2*)&Cf[(size_t)(row0 + 8) * DMODEL + col] = make_float2(v10, v11);
            }
        }
    }
}

__global__ __launch_bounds__(256, 2)
void proj_gemm_kernel(const float* __restrict__ bq, const float* __restrict__ bk,
                      const float* __restrict__ bv)
{
    int z = blockIdx.z;
    const float* bias = (z == 0) ? bq : (z == 1) ? bk : bv;
    gemm_body(g_Xhi[z], g_Xlo[z], g_Whi[z], g_Wlo[z], bias,
              g_Phi[z], g_Plo[z], nullptr, 0);
}

__global__ __launch_bounds__(256, 2)
void out_gemm_kernel(const float* __restrict__ bo, float* __restrict__ out)
{
    gemm_body(g_Ohi, g_Olo, g_Whi[3], g_Wlo[3], bo, nullptr, nullptr, out, 1);
}

// ---------------------------------------------------------------------------
// Flash attention, HMMA bf16x3. CTA = 128 q-rows x 1 head, 8 warps (m16n64),
// K/V double-buffered cp.async. smem 110592 B -> 2 CTAs/SM.
// ---------------------------------------------------------------------------
#define ATP 144
#define AKV_TILE (64 * ATP)       // 9216 per matrix
#define AQ_TILE  (128 * ATP)      // 18432
#define A_QHI 0
#define A_QLO AQ_TILE
#define A_KV  (2 * AQ_TILE)       // stage s at A_KV + s*4*AKV_TILE
#define A_SMEM (2 * AQ_TILE + 2 * 4 * AKV_TILE)   // 110592

__device__ __forceinline__ void attn_load_kv(
    uint32_t st, const __nv_bfloat16* __restrict__ khi, const __nv_bfloat16* __restrict__ klo,
    const __nv_bfloat16* __restrict__ vhi, const __nv_bfloat16* __restrict__ vlo,
    int j0, int colBase, int tid)
{
    const __nv_bfloat16* srcs[4] = {khi, klo, vhi, vlo};
    #pragma unroll
    for (int i = 0; i < 8; i++) {
        int idx = tid + i * 256;          // 0..2047
        int mat = idx >> 9;               // 512 per matrix
        int j = idx & 511;
        int r = j >> 3, c = j & 7;
        uint32_t so = (uint32_t)r * ATP + c * 16;
        CP16(st + mat * AKV_TILE + so,
             srcs[mat] + (size_t)(j0 + r) * DMODEL + colBase + c * 8);
    }
    CP_COMMIT();
}

__global__ __launch_bounds__(256, 2)
void attn_kernel()
{
    extern __shared__ __align__(128) char smem[];
    uint32_t sb = smem_u32(smem);
    const int tid = threadIdx.x;
    const int wid = tid >> 5, lane = tid & 31;
    const int gid = lane >> 2, tig = lane & 3;
    const int qt = blockIdx.x, h = blockIdx.y;
    const int r0 = qt * 128;
    const int colBase = h * HDK;

    const __nv_bfloat16* qhi = g_Phi[0]; const __nv_bfloat16* qlo = g_Plo[0];
    const __nv_bfloat16* khi = g_Phi[1]; const __nv_bfloat16* klo = g_Plo[1];
    const __nv_bfloat16* vhi = g_Phi[2]; const __nv_bfloat16* vlo = g_Plo[2];

    // Q tiles hi/lo: 128 rows x 8 x 2 = 2048 CP16 / 256 thr
    #pragma unroll
    for (int i = 0; i < 8; i++) {
        int idx = tid + i * 256;
        int mat = idx >> 10;              // 0=hi, 1=lo (1024 each)
        int j = idx & 1023;
        int r = j >> 3, c = j & 7;
        uint32_t so = (uint32_t)r * ATP + c * 16;
        CP16(sb + (mat ? A_QLO : A_QHI) + so,
             (mat ? qlo : qhi) + (size_t)(r0 + r) * DMODEL + colBase + c * 8);
    }
    CP_COMMIT();
    // K/V tile 0 into stage 0
    attn_load_kv(sb + A_KV, khi, klo, vhi, vlo, 0, colBase, tid);
    CP_WAIT1();                          // Q ready
    __syncthreads();

    // Q fragments: warp wid owns rows wid*16..wid*16+15
    uint32_t qfh[4][4], qfl[4][4];
    #pragma unroll
    for (int ks = 0; ks < 4; ks++) {
        ldsm4(qfh[ks], a_addr(sb + A_QHI, wid * 16, ks * 32, lane, ATP));
        ldsm4(qfl[ks], a_addr(sb + A_QLO, wid * 16, ks * 32, lane, ATP));
    }

    float O[8][4];
    #pragma unroll
    for (int a = 0; a < 8; a++)
        #pragma unroll
        for (int b = 0; b < 4; b++) O[a][b] = 0.f;
    float m0 = -INFINITY, m1 = -INFINITY, l0 = 0.f, l1 = 0.f;
    const float scale = 0.125f;

    for (int jt = 0; jt < 32; jt++) {
        uint32_t stCur = sb + A_KV + (jt & 1) * (4 * AKV_TILE);
        if (jt + 1 < 32) {
            attn_load_kv(sb + A_KV + ((jt + 1) & 1) * (4 * AKV_TILE),
                         khi, klo, vhi, vlo, (jt + 1) * 64, colBase, tid);
            CP_WAIT1();
        } else {
            CP_WAIT0();
        }
        __syncthreads();

        // ---- scores ----
        float sc[8][4];
        #pragma unroll
        for (int a = 0; a < 8; a++)
            #pragma unroll
            for (int b = 0; b < 4; b++) sc[a][b] = 0.f;

        #pragma unroll
        for (int ks = 0; ks < 4; ks++) {
            int kb = ks * 32;
            #pragma unroll
            for (int nt2 = 0; nt2 < 4; nt2++) {
                uint32_t bh[4], bl[4];
                ldsm4(bh, b_addr(stCur,            nt2 * 16, kb, lane, ATP));
                ldsm4(bl, b_addr(stCur + AKV_TILE, nt2 * 16, kb, lane, ATP));
                mma16816(sc[nt2*2],   qfh[ks], bh[0], bh[1]);
                mma16816(sc[nt2*2],   qfh[ks], bl[0], bl[1]);
                mma16816(sc[nt2*2],   qfl[ks], bh[0], bh[1]);
                mma16816(sc[nt2*2+1], qfh[ks], bh[2], bh[3]);
                mma16816(sc[nt2*2+1], qfh[ks], bl[2], bl[3]);
                mma16816(sc[nt2*2+1], qfl[ks], bh[2], bh[3]);
            }
        }

        // ---- online softmax ----
        float mx0 = -INFINITY, mx1 = -INFINITY;
        #pragma unroll
        for (int nt = 0; nt < 8; nt++) {
            mx0 = fmaxf(mx0, fmaxf(sc[nt][0], sc[nt][1]));
            mx1 = fmaxf(mx1, fmaxf(sc[nt][2], sc[nt][3]));
        }
        mx0 *= scale; mx1 *= scale;
        mx0 = fmaxf(mx0, __shfl_xor_sync(0xffffffffu, mx0, 1));
        mx0 = fmaxf(mx0, __shfl_xor_sync(0xffffffffu, mx0, 2));
        mx1 = fmaxf(mx1, __shfl_xor_sync(0xffffffffu, mx1, 1));
        mx1 = fmaxf(mx1, __shfl_xor_sync(0xffffffffu, mx1, 2));
        float mn0 = fmaxf(m0, mx0), mn1 = fmaxf(m1, mx1);
        float al0 = __expf(m0 - mn0), al1 = __expf(m1 - mn1);

        float s0 = 0.f, s1 = 0.f;
        #pragma unroll
        for (int nt = 0; nt < 8; nt++) {
            float p0 = __expf(sc[nt][0] * scale - mn0);
            float p1 = __expf(sc[nt][1] * scale - mn0);
            float p2 = __expf(sc[nt][2] * scale - mn1);
            float p3 = __expf(sc[nt][3] * scale - mn1);
            sc[nt][0] = p0; sc[nt][1] = p1; sc[nt][2] = p2; sc[nt][3] = p3;
            s0 += p0 + p1; s1 += p2 + p3;
        }
        s0 += __shfl_xor_sync(0xffffffffu, s0, 1);
        s0 += __shfl_xor_sync(0xffffffffu, s0, 2);
        s1 += __shfl_xor_sync(0xffffffffu, s1, 1);
        s1 += __shfl_xor_sync(0xffffffffu, s1, 2);
        l0 = l0 * al0 + s0; l1 = l1 * al1 + s1;
        m0 = mn0; m1 = mn1;
        #pragma unroll
        for (int nt = 0; nt < 8; nt++) {
            O[nt][0] *= al0; O[nt][1] *= al0;
            O[nt][2] *= al1; O[nt][3] *= al1;
        }

        // ---- PV ----
        #pragma unroll
        for (int kt = 0; kt < 4; kt++) {
            uint32_t ph[4], pl[4];
            hilo_pack(sc[2*kt][0],   sc[2*kt][1],   ph[0], pl[0]);
            hilo_pack(sc[2*kt][2],   sc[2*kt][3],   ph[1], pl[1]);
            hilo_pack(sc[2*kt+1][0], sc[2*kt+1][1], ph[2], pl[2]);
            hilo_pack(sc[2*kt+1][2], sc[2*kt+1][3], ph[3], pl[3]);
            #pragma unroll
            for (int nt2 = 0; nt2 < 4; nt2++) {
                uint32_t vh[4], vl[4];
                ldsm4t(vh, v_addr(stCur + 2 * AKV_TILE, kt * 16, nt2 * 32, lane, ATP));
                ldsm4t(vl, v_addr(stCur + 3 * AKV_TILE, kt * 16, nt2 * 32, lane, ATP));
                mma16816(O[nt2*2],   ph, vh[0], vh[1]);
                mma16816(O[nt2*2],   ph, vl[0], vl[1]);
                mma16816(O[nt2*2],   pl, vh[0], vh[1]);
                mma16816(O[nt2*2+1], ph, vh[2], vh[3]);
                mma16816(O[nt2*2+1], ph, vl[2], vl[3]);
                mma16816(O[nt2*2+1], pl, vh[2], vh[3]);
            }
        }
        __syncthreads();   // compute done before buffer jt&1 is overwritten
    }

    // ---- epilogue ----
    float inv0 = 1.f / l0, inv1 = 1.f / l1;
    int rowA = r0 + wid * 16 + gid;
    #pragma unroll
    for (int nt = 0; nt < 8; nt++) {
        int col = colBase + nt * 8 + tig * 2;
        uint32_t ph, pl;
        hilo_pack(O[nt][0] * inv0, O[nt][1] * inv0, ph, pl);
        *(uint32_t*)&g_Ohi[(size_t)rowA * DMODEL + col] = ph;
        *(uint32_t*)&g_Olo[(size_t)rowA * DMODEL + col] = pl;
        hilo_pack(O[nt][2] * inv1, O[nt][3] * inv1, ph, pl);
        *(uint32_t*)&g_Ohi[(size_t)(rowA + 8) * DMODEL + col] = ph;
        *(uint32_t*)&g_Olo[(size_t)(rowA + 8) * DMODEL + col] = pl;
    }
}

// ---------------------------------------------------------------------------
extern "C" void kernel_launch(void* const* d_in, const int* in_sizes, int n_in,
                              void* d_out, int out_size)
{
    const float* Q  = (const float*)d_in[0];
    const float* K  = (const float*)d_in[1];
    const float* V  = (const float*)d_in[2];
    const float* Wq = (const float*)d_in[3];
    const float* bq = (const float*)d_in[4];
    const float* Wk = (const float*)d_in[5];
    const float* bk = (const float*)d_in[6];
    const float* Wv = (const float*)d_in[7];
    const float* bv = (const float*)d_in[8];
    const float* Wo = (const float*)d_in[9];
    const float* bo = (const float*)d_in[10];
    float* out = (float*)d_out;

    cudaFuncSetAttribute(proj_gemm_kernel, cudaFuncAttributeMaxDynamicSharedMemorySize, G_SMEM);
    cudaFuncSetAttribute(out_gemm_kernel,  cudaFuncAttributeMaxDynamicSharedMemorySize, G_SMEM);
    cudaFuncSetAttribute(attn_kernel,      cudaFuncAttributeMaxDynamicSharedMemorySize, A_SMEM);

    conv_in_kernel<<<dim3(SEQ * DMODEL / 1024, 3), 256>>>(Q, K, V);
    conv_w3_kernel<<<dim3(16, 1, 48), 256>>>(Wq, Wk, Wv);
    conv_wo_kernel<<<dim3(16, 16, 1), 256>>>(Wo);

    proj_gemm_kernel<<<dim3(16, 8, 3), 256, G_SMEM>>>(bq, bk, bv);
    attn_kernel<<<dim3(SEQ / 128, NH), 256, A_SMEM>>>();
    out_gemm_kernel<<<dim3(16, 8), 256, G_SMEM>>>(bo, out);
}

// round 9
// speedup vs baseline: 2.8903x; 1.0071x over previous
#include <cuda_runtime.h>
#include <cuda_bf16.h>
#include <math.h>
#include <stdint.h>

#define SEQ 2048
#define DMODEL 1024
#define NH 16
#define HDK 64

// ---------------------------------------------------------------------------
// Scratch (__device__ globals: allocation-free contract). All bf16 hi/lo pairs.
// ---------------------------------------------------------------------------
__device__ __nv_bfloat16 g_Xhi[3][SEQ * DMODEL];    // model inputs Q,K,V
__device__ __nv_bfloat16 g_Xlo[3][SEQ * DMODEL];
__device__ __nv_bfloat16 g_Whi[4][DMODEL * DMODEL]; // Wq,Wk,Wv,Wo as [N][K]
__device__ __nv_bfloat16 g_Wlo[4][DMODEL * DMODEL];
__device__ __nv_bfloat16 g_Phi[3][SEQ * DMODEL];    // projected q,k,v [S][h*64+dk]
__device__ __nv_bfloat16 g_Plo[3][SEQ * DMODEL];
__device__ __nv_bfloat16 g_Ohi[SEQ * DMODEL];       // concat (attention out)
__device__ __nv_bfloat16 g_Olo[SEQ * DMODEL];

// ---------------------------------------------------------------------------
// Helpers
// ---------------------------------------------------------------------------
__device__ __forceinline__ uint32_t smem_u32(const void* p) {
    uint32_t a;
    asm("{ .reg .u64 t; cvta.to.shared.u64 t, %1; cvt.u32.u64 %0, t; }" : "=r"(a) : "l"(p));
    return a;
}

#define CP16(dst, src) \
    asm volatile("cp.async.cg.shared.global [%0], [%1], 16;" :: "r"((uint32_t)(dst)), "l"(src) : "memory")
#define CP_COMMIT() asm volatile("cp.async.commit_group;" ::: "memory")
#define CP_WAIT0()  asm volatile("cp.async.wait_group 0;" ::: "memory")
#define CP_WAIT1()  asm volatile("cp.async.wait_group 1;" ::: "memory")

__device__ __forceinline__ void ldsm4(uint32_t* r, uint32_t addr) {
    asm volatile("ldmatrix.sync.aligned.m8n8.x4.shared.b16 {%0,%1,%2,%3}, [%4];"
                 : "=r"(r[0]), "=r"(r[1]), "=r"(r[2]), "=r"(r[3]) : "r"(addr));
}
__device__ __forceinline__ void ldsm4t(uint32_t* r, uint32_t addr) {
    asm volatile("ldmatrix.sync.aligned.m8n8.x4.trans.shared.b16 {%0,%1,%2,%3}, [%4];"
                 : "=r"(r[0]), "=r"(r[1]), "=r"(r[2]), "=r"(r[3]) : "r"(addr));
}
__device__ __forceinline__ void mma16816(float* c, const uint32_t* a, uint32_t b0, uint32_t b1) {
    asm volatile("mma.sync.aligned.m16n8k16.row.col.f32.bf16.bf16.f32 "
                 "{%0,%1,%2,%3}, {%4,%5,%6,%7}, {%8,%9}, {%0,%1,%2,%3};"
                 : "+f"(c[0]), "+f"(c[1]), "+f"(c[2]), "+f"(c[3])
                 : "r"(a[0]), "r"(a[1]), "r"(a[2]), "r"(a[3]), "r"(b0), "r"(b1));
}

__device__ __forceinline__ uint32_t packbf(float a, float b) {
    __nv_bfloat162 t = __floats2bfloat162_rn(a, b);
    return *reinterpret_cast<uint32_t*>(&t);
}
__device__ __forceinline__ void split2(float x, float& hf, float& lf) {
    hf = __bfloat162float(__float2bfloat16(x));
    lf = x - hf;
}
// Truncation-based hi/lo split-and-pack (cheap: PRMT + 2 LOP + 2 FADD + pack)
__device__ __forceinline__ void hilo_pack(float x, float y, uint32_t& ph, uint32_t& pl) {
    uint32_t ux = __float_as_uint(x), uy = __float_as_uint(y);
    ph = __byte_perm(ux, uy, 0x7632);   // {hi16(x), hi16(y)}
    float lx = x - __uint_as_float(ux & 0xFFFF0000u);
    float ly = y - __uint_as_float(uy & 0xFFFF0000u);
    pl = packbf(lx, ly);
}

// ldmatrix address generators, parametric row pitch P (bytes).
__device__ __forceinline__ uint32_t a_addr(uint32_t tb, int r0, int kb, int lane, int P) {
    int sub = lane >> 3, ll = lane & 7;
    return tb + (uint32_t)(r0 + ((sub & 1) << 3) + ll) * P + kb + ((sub >> 1) << 4);
}
__device__ __forceinline__ uint32_t b_addr(uint32_t tb, int n0, int kb, int lane, int P) {
    int sub = lane >> 3, ll = lane & 7;
    return tb + (uint32_t)(n0 + ((sub >> 1) << 3) + ll) * P + kb + ((sub & 1) << 4);
}
__device__ __forceinline__ uint32_t v_addr(uint32_t tb, int k0, int nb, int lane, int P) {
    int sub = lane >> 3, ll = lane & 7;
    return tb + (uint32_t)(k0 + ((sub & 1) << 3) + ll) * P + nb + ((sub >> 1) << 4);
}

// ---------------------------------------------------------------------------
// Conversion kernels
// ---------------------------------------------------------------------------
__global__ void conv_in_kernel(const float* __restrict__ Q, const float* __restrict__ K,
                               const float* __restrict__ V)
{
    int z = blockIdx.y;
    const float* src = (z == 0) ? Q : (z == 1) ? K : V;
    #pragma unroll
    for (int k = 0; k < 2; k++) {
        size_t i = ((size_t)blockIdx.x * 256 + threadIdx.x) * 4 + (size_t)k * (SEQ * DMODEL / 2);
        float4 v = *(const float4*)(src + i);
        float h0,l0,h1,l1,h2,l2,h3,l3;
        split2(v.x,h0,l0); split2(v.y,h1,l1); split2(v.z,h2,l2); split2(v.w,h3,l3);
        *(uint32_t*)&g_Xhi[z][i]   = packbf(h0,h1);
        *(uint32_t*)&g_Xhi[z][i+2] = packbf(h2,h3);
        *(uint32_t*)&g_Xlo[z][i]   = packbf(l0,l1);
        *(uint32_t*)&g_Xlo[z][i+2] = packbf(l2,l3);
    }
}

__device__ __forceinline__ void conv_w_body(const float* __restrict__ src,
                                            __nv_bfloat16* __restrict__ dhi,
                                            __nv_bfloat16* __restrict__ dlo,
                                            int R, int C, int bx, int by)
{
    __shared__ float t[64][65];
    int r0 = bx * 64, c0 = by * 64;
    int tid = threadIdx.x;
    #pragma unroll
    for (int i = 0; i < 16; i++) {
        int idx = tid + i * 256;
        int rr = idx >> 6, cc = idx & 63;
        t[cc][rr] = src[(size_t)(r0 + rr) * C + c0 + cc];
    }
    __syncthreads();
    #pragma unroll
    for (int i = 0; i < 16; i++) {
        int idx = tid + i * 256;
        int rr = idx >> 6, cc = idx & 63;
        float h, l;
        split2(t[rr][cc], h, l);
        dhi[(size_t)(c0 + rr) * R + r0 + cc] = __float2bfloat16(h);
        dlo[(size_t)(c0 + rr) * R + r0 + cc] = __float2bfloat16(l);
    }
}

__global__ void conv_w3_kernel(const float* __restrict__ Wq, const float* __restrict__ Wk,
                               const float* __restrict__ Wv)
{
    int which = blockIdx.z >> 4, zz = blockIdx.z & 15;
    const float* src = (which == 0) ? Wq : (which == 1) ? Wk : Wv;
    conv_w_body(src + (size_t)zz * DMODEL * HDK,
                &g_Whi[which][(size_t)zz * DMODEL * HDK],
                &g_Wlo[which][(size_t)zz * DMODEL * HDK],
                1024, 64, blockIdx.x, 0);
}

__global__ void conv_wo_kernel(const float* __restrict__ Wo)
{
    conv_w_body(Wo, g_Whi[3], g_Wlo[3], 1024, 1024, blockIdx.x, blockIdx.y);
}

// ---------------------------------------------------------------------------
// HMMA bf16x3 GEMM: C = A[S][1024] * B^T ([N][K]) + bias.
// CTA tile 128x64, 8 warps (warp 32x32), K-chunk 32, 3-stage cp.async,
// ONE __syncthreads per chunk. smem 92160 B -> 2 CTAs/SM.
// ---------------------------------------------------------------------------
#define TPG 80
#define GA_MAT (128 * TPG)                 // 10240
#define GB_MAT (64 * TPG)                  // 5120
#define G_STAGE (2 * GA_MAT + 2 * GB_MAT)  // 30720
#define G_SMEM  (3 * G_STAGE)              // 92160
#define G_NCHUNK 32

__device__ __forceinline__ void g_load_chunk(
    uint32_t st,
    const __nv_bfloat16* __restrict__ Ahi, const __nv_bfloat16* __restrict__ Alo,
    const __nv_bfloat16* __restrict__ Bhi, const __nv_bfloat16* __restrict__ Blo,
    int m0, int n0, int k0, int tid)
{
    #pragma unroll
    for (int i = 0; i < 4; i++) {              // A hi (i=0,1) / A lo (i=2,3)
        int idx = tid + i * 256;               // 0..1023
        int sub = idx >> 9;
        int j = idx & 511;
        int r = j >> 2, c = j & 3;
        const __nv_bfloat16* src = sub ? Alo : Ahi;
        CP16(st + sub * GA_MAT + (uint32_t)r * TPG + c * 16,
             src + (size_t)(m0 + r) * DMODEL + k0 + c * 8);
    }
    #pragma unroll
    for (int i = 0; i < 2; i++) {              // B hi (i=0) / B lo (i=1)
        int idx = tid + i * 256;               // 0..511
        int sub = idx >> 8;
        int j = idx & 255;
        int r = j >> 2, c = j & 3;
        const __nv_bfloat16* src = sub ? Blo : Bhi;
        CP16(st + 2 * GA_MAT + sub * GB_MAT + (uint32_t)r * TPG + c * 16,
             src + (size_t)(n0 + r) * DMODEL + k0 + c * 8);
    }
    CP_COMMIT();
}

__device__ __forceinline__ void g_compute_chunk(uint32_t st, int lane, int wr, int wc,
                                                float C[2][4][4])
{
    #pragma unroll
    for (int ks = 0; ks < 2; ks++) {
        int kb = ks * 32;
        uint32_t ah[2][4], al[2][4];
        #pragma unroll
        for (int mt = 0; mt < 2; mt++) {
            ldsm4(ah[mt], a_addr(st,          wr * 32 + mt * 16, kb, lane, TPG));
            ldsm4(al[mt], a_addr(st + GA_MAT, wr * 32 + mt * 16, kb, lane, TPG));
        }
        #pragma unroll
        for (int nt2 = 0; nt2 < 2; nt2++) {
            uint32_t bh[4], bl[4];
            ldsm4(bh, b_addr(st + 2 * GA_MAT,          wc * 32 + nt2 * 16, kb, lane, TPG));
            ldsm4(bl, b_addr(st + 2 * GA_MAT + GB_MAT, wc * 32 + nt2 * 16, kb, lane, TPG));
            #pragma unroll
            for (int mt = 0; mt < 2; mt++) {
                mma16816(C[mt][nt2*2],   ah[mt], bh[0], bh[1]);
                mma16816(C[mt][nt2*2],   ah[mt], bl[0], bl[1]);
                mma16816(C[mt][nt2*2],   al[mt], bh[0], bh[1]);
                mma16816(C[mt][nt2*2+1], ah[mt], bh[2], bh[3]);
                mma16816(C[mt][nt2*2+1], ah[mt], bl[2], bl[3]);
                mma16816(C[mt][nt2*2+1], al[mt], bh[2], bh[3]);
            }
        }
    }
}

template <int MODE>   // 0: write bf16 hi/lo, 1: write fp32
__device__ __forceinline__ void gemm_body(
    const __nv_bfloat16* __restrict__ Ahi, const __nv_bfloat16* __restrict__ Alo,
    const __nv_bfloat16* __restrict__ Bhi, const __nv_bfloat16* __restrict__ Blo,
    const float* __restrict__ bias,
    __nv_bfloat16* __restrict__ Chi, __nv_bfloat16* __restrict__ Clo,
    float* __restrict__ Cf)
{
    extern __shared__ __align__(128) char smem[];
    uint32_t sb = smem_u32(smem);
    const int tid = threadIdx.x;
    const int wid = tid >> 5, lane = tid & 31;
    const int wr = wid & 3, wc = wid >> 2;
    const int m0 = blockIdx.x * 128, n0 = blockIdx.y * 64;

    float C[2][4][4];
    #pragma unroll
    for (int a = 0; a < 2; a++)
        #pragma unroll
        for (int b = 0; b < 4; b++)
            #pragma unroll
            for (int c = 0; c < 4; c++) C[a][b][c] = 0.f;

    g_load_chunk(sb,           Ahi, Alo, Bhi, Blo, m0, n0, 0,  tid);
    g_load_chunk(sb + G_STAGE, Ahi, Alo, Bhi, Blo, m0, n0, 32, tid);

    for (int i = 0; i < G_NCHUNK; i++) {
        if (i + 1 < G_NCHUNK) { CP_WAIT1(); } else { CP_WAIT0(); }
        __syncthreads();
        if (i + 2 < G_NCHUNK)
            g_load_chunk(sb + ((i + 2) % 3) * G_STAGE, Ahi, Alo, Bhi, Blo,
                         m0, n0, (i + 2) * 32, tid);
        g_compute_chunk(sb + (i % 3) * G_STAGE, lane, wr, wc, C);
    }

    const int gid = lane >> 2, tig = lane & 3;
    #pragma unroll
    for (int mt = 0; mt < 2; mt++) {
        int row0 = m0 + wr * 32 + mt * 16 + gid;
        #pragma unroll
        for (int nt = 0; nt < 4; nt++) {
            int col = n0 + wc * 32 + nt * 8 + tig * 2;
            float b0 = bias[col], b1 = bias[col + 1];
            float v00 = C[mt][nt][0] + b0, v01 = C[mt][nt][1] + b1;
            float v10 = C[mt][nt][2] + b0, v11 = C[mt][nt][3] + b1;
            if (MODE == 0) {
                uint32_t ph, pl;
                hilo_pack(v00, v01, ph, pl);
                *(uint32_t*)&Chi[(size_t)row0 * DMODEL + col] = ph;
                *(uint32_t*)&Clo[(size_t)row0 * DMODEL + col] = pl;
                hilo_pack(v10, v11, ph, pl);
                *(uint32_t*)&Chi[(size_t)(row0 + 8) * DMODEL + col] = ph;
                *(uint32_t*)&Clo[(size_t)(row0 + 8) * DMODEL + col] = pl;
            } else {
                *(float2*)&Cf[(size_t)row0 * DMODEL + col] = make_float2(v00, v01);
                *(float2*)&Cf[(size_t)(row0 + 8) * DMODEL + col] = make_float2(v10, v11);
            }
        }
    }
}

__global__ __launch_bounds__(256, 2)
void proj_gemm_kernel(const float* __restrict__ bq, const float* __restrict__ bk,
                      const float* __restrict__ bv)
{
    int z = blockIdx.z;
    const float* bias = (z == 0) ? bq : (z == 1) ? bk : bv;
    gemm_body<0>(g_Xhi[z], g_Xlo[z], g_Whi[z], g_Wlo[z], bias,
                 g_Phi[z], g_Plo[z], nullptr);
}

__global__ __launch_bounds__(256, 2)
void out_gemm_kernel(const float* __restrict__ bo, float* __restrict__ out)
{
    gemm_body<1>(g_Ohi, g_Olo, g_Whi[3], g_Wlo[3], bo, nullptr, nullptr, out);
}

// ---------------------------------------------------------------------------
// Flash attention, HMMA bf16x3, NO max-tracking (scores bounded: |s|<~8 << 88).
// CTA = 128 q-rows x 1 head, 8 warps (m16n64), K/V double-buffered.
// One __syncthreads per jt. smem 110592 B -> 2 CTAs/SM.
// ---------------------------------------------------------------------------
#define ATP 144
#define AKV_TILE (64 * ATP)
#define AQ_TILE  (128 * ATP)
#define A_QHI 0
#define A_QLO AQ_TILE
#define A_KV  (2 * AQ_TILE)
#define A_SMEM (2 * AQ_TILE + 2 * 4 * AKV_TILE)   // 110592

__device__ __forceinline__ void attn_load_kv(
    uint32_t st, const __nv_bfloat16* __restrict__ khi, const __nv_bfloat16* __restrict__ klo,
    const __nv_bfloat16* __restrict__ vhi, const __nv_bfloat16* __restrict__ vlo,
    int j0, int colBase, int tid)
{
    const __nv_bfloat16* srcs[4] = {khi, klo, vhi, vlo};
    #pragma unroll
    for (int i = 0; i < 8; i++) {
        int idx = tid + i * 256;
        int mat = idx >> 9;
        int j = idx & 511;
        int r = j >> 3, c = j & 7;
        uint32_t so = (uint32_t)r * ATP + c * 16;
        CP16(st + mat * AKV_TILE + so,
             srcs[mat] + (size_t)(j0 + r) * DMODEL + colBase + c * 8);
    }
    CP_COMMIT();
}

__global__ __launch_bounds__(256, 2)
void attn_kernel()
{
    extern __shared__ __align__(128) char smem[];
    uint32_t sb = smem_u32(smem);
    const int tid = threadIdx.x;
    const int wid = tid >> 5, lane = tid & 31;
    const int gid = lane >> 2, tig = lane & 3;
    const int qt = blockIdx.x, h = blockIdx.y;
    const int r0 = qt * 128;
    const int colBase = h * HDK;

    const __nv_bfloat16* qhi = g_Phi[0]; const __nv_bfloat16* qlo = g_Plo[0];
    const __nv_bfloat16* khi = g_Phi[1]; const __nv_bfloat16* klo = g_Plo[1];
    const __nv_bfloat16* vhi = g_Phi[2]; const __nv_bfloat16* vlo = g_Plo[2];

    // Q tiles hi/lo
    #pragma unroll
    for (int i = 0; i < 8; i++) {
        int idx = tid + i * 256;
        int mat = idx >> 10;
        int j = idx & 1023;
        int r = j >> 3, c = j & 7;
        uint32_t so = (uint32_t)r * ATP + c * 16;
        CP16(sb + (mat ? A_QLO : A_QHI) + so,
             (mat ? qlo : qhi) + (size_t)(r0 + r) * DMODEL + colBase + c * 8);
    }
    CP_COMMIT();
    attn_load_kv(sb + A_KV, khi, klo, vhi, vlo, 0, colBase, tid);
    CP_WAIT1();                          // Q arrived (KV0 still in flight)
    __syncthreads();

    uint32_t qfh[4][4], qfl[4][4];
    #pragma unroll
    for (int ks = 0; ks < 4; ks++) {
        ldsm4(qfh[ks], a_addr(sb + A_QHI, wid * 16, ks * 32, lane, ATP));
        ldsm4(qfl[ks], a_addr(sb + A_QLO, wid * 16, ks * 32, lane, ATP));
    }

    float O[8][4];
    #pragma unroll
    for (int a = 0; a < 8; a++)
        #pragma unroll
        for (int b = 0; b < 4; b++) O[a][b] = 0.f;
    float l0 = 0.f, l1 = 0.f;
    const float CE = 0.125f * 1.44269504088896f;   // scale * log2(e)

    for (int jt = 0; jt < 32; jt++) {
        CP_WAIT0();                       // KV jt arrived
        __syncthreads();                  // all warps done with other buffer
        if (jt + 1 < 32)
            attn_load_kv(sb + A_KV + ((jt + 1) & 1) * (4 * AKV_TILE),
                         khi, klo, vhi, vlo, (jt + 1) * 64, colBase, tid);
        uint32_t stCur = sb + A_KV + (jt & 1) * (4 * AKV_TILE);

        // ---- scores ----
        float sc[8][4];
        #pragma unroll
        for (int a = 0; a < 8; a++)
            #pragma unroll
            for (int b = 0; b < 4; b++) sc[a][b] = 0.f;

        #pragma unroll
        for (int ks = 0; ks < 4; ks++) {
            int kb = ks * 32;
            #pragma unroll
            for (int nt2 = 0; nt2 < 4; nt2++) {
                uint32_t bh[4], bl[4];
                ldsm4(bh, b_addr(stCur,            nt2 * 16, kb, lane, ATP));
                ldsm4(bl, b_addr(stCur + AKV_TILE, nt2 * 16, kb, lane, ATP));
                mma16816(sc[nt2*2],   qfh[ks], bh[0], bh[1]);
                mma16816(sc[nt2*2],   qfh[ks], bl[0], bl[1]);
                mma16816(sc[nt2*2],   qfl[ks], bh[0], bh[1]);
                mma16816(sc[nt2*2+1], qfh[ks], bh[2], bh[3]);
                mma16816(sc[nt2*2+1], qfh[ks], bl[2], bl[3]);
                mma16816(sc[nt2*2+1], qfl[ks], bh[2], bh[3]);
            }
        }

        // ---- exp (no max subtraction; bounded scores) ----
        #pragma unroll
        for (int nt = 0; nt < 8; nt++) {
            float p0 = exp2f(sc[nt][0] * CE);
            float p1 = exp2f(sc[nt][1] * CE);
            float p2 = exp2f(sc[nt][2] * CE);
            float p3 = exp2f(sc[nt][3] * CE);
            sc[nt][0] = p0; sc[nt][1] = p1; sc[nt][2] = p2; sc[nt][3] = p3;
            l0 += p0 + p1; l1 += p2 + p3;
        }

        // ---- PV ----
        #pragma unroll
        for (int kt = 0; kt < 4; kt++) {
            uint32_t ph[4], pl[4];
            hilo_pack(sc[2*kt][0],   sc[2*kt][1],   ph[0], pl[0]);
            hilo_pack(sc[2*kt][2],   sc[2*kt][3],   ph[1], pl[1]);
            hilo_pack(sc[2*kt+1][0], sc[2*kt+1][1], ph[2], pl[2]);
            hilo_pack(sc[2*kt+1][2], sc[2*kt+1][3], ph[3], pl[3]);
            #pragma unroll
            for (int nt2 = 0; nt2 < 4; nt2++) {
                uint32_t vh[4], vl[4];
                ldsm4t(vh, v_addr(stCur + 2 * AKV_TILE, kt * 16, nt2 * 32, lane, ATP));
                ldsm4t(vl, v_addr(stCur + 3 * AKV_TILE, kt * 16, nt2 * 32, lane, ATP));
                mma16816(O[nt2*2],   ph, vh[0], vh[1]);
                mma16816(O[nt2*2],   ph, vl[0], vl[1]);
                mma16816(O[nt2*2],   pl, vh[0], vh[1]);
                mma16816(O[nt2*2+1], ph, vh[2], vh[3]);
                mma16816(O[nt2*2+1], ph, vl[2], vl[3]);
                mma16816(O[nt2*2+1], pl, vh[2], vh[3]);
            }
        }
    }

    // ---- deferred row-sum reduction (over tig group) ----
    l0 += __shfl_xor_sync(0xffffffffu, l0, 1);
    l0 += __shfl_xor_sync(0xffffffffu, l0, 2);
    l1 += __shfl_xor_sync(0xffffffffu, l1, 1);
    l1 += __shfl_xor_sync(0xffffffffu, l1, 2);

    float inv0 = 1.f / l0, inv1 = 1.f / l1;
    int rowA = r0 + wid * 16 + gid;
    #pragma unroll
    for (int nt = 0; nt < 8; nt++) {
        int col = colBase + nt * 8 + tig * 2;
        uint32_t ph, pl;
        hilo_pack(O[nt][0] * inv0, O[nt][1] * inv0, ph, pl);
        *(uint32_t*)&g_Ohi[(size_t)rowA * DMODEL + col] = ph;
        *(uint32_t*)&g_Olo[(size_t)rowA * DMODEL + col] = pl;
        hilo_pack(O[nt][2] * inv1, O[nt][3] * inv1, ph, pl);
        *(uint32_t*)&g_Ohi[(size_t)(rowA + 8) * DMODEL + col] = ph;
        *(uint32_t*)&g_Olo[(size_t)(rowA + 8) * DMODEL + col] = pl;
    }
}

// ---------------------------------------------------------------------------
extern "C" void kernel_launch(void* const* d_in, const int* in_sizes, int n_in,
                              void* d_out, int out_size)
{
    const float* Q  = (const float*)d_in[0];
    const float* K  = (const float*)d_in[1];
    const float* V  = (const float*)d_in[2];
    const float* Wq = (const float*)d_in[3];
    const float* bq = (const float*)d_in[4];
    const float* Wk = (const float*)d_in[5];
    const float* bk = (const float*)d_in[6];
    const float* Wv = (const float*)d_in[7];
    const float* bv = (const float*)d_in[8];
    const float* Wo = (const float*)d_in[9];
    const float* bo = (const float*)d_in[10];
    float* out = (float*)d_out;

    cudaFuncSetAttribute(proj_gemm_kernel, cudaFuncAttributeMaxDynamicSharedMemorySize, G_SMEM);
    cudaFuncSetAttribute(out_gemm_kernel,  cudaFuncAttributeMaxDynamicSharedMemorySize, G_SMEM);
    cudaFuncSetAttribute(attn_kernel,      cudaFuncAttributeMaxDynamicSharedMemorySize, A_SMEM);

    conv_in_kernel<<<dim3(SEQ * DMODEL / 2048, 3), 256>>>(Q, K, V);
    conv_w3_kernel<<<dim3(16, 1, 48), 256>>>(Wq, Wk, Wv);
    conv_wo_kernel<<<dim3(16, 16, 1), 256>>>(Wo);

    proj_gemm_kernel<<<dim3(16, 16, 3), 256, G_SMEM>>>(bq, bk, bv);
    attn_kernel<<<dim3(SEQ / 128, NH), 256, A_SMEM>>>();
    out_gemm_kernel<<<dim3(16, 16), 256, G_SMEM>>>(bo, out);
}

// round 10
// speedup vs baseline: 3.1762x; 1.0989x over previous
#include <cuda_runtime.h>
#include <cuda_fp16.h>
#include <math.h>
#include <stdint.h>

#define SEQ 2048
#define DMODEL 1024
#define NH 16
#define HDK 64

// ---------------------------------------------------------------------------
// Scratch (__device__ globals). All fp16 hi/lo pairs.
// ---------------------------------------------------------------------------
__device__ __half g_Xhi[3][SEQ * DMODEL];    // model inputs Q,K,V
__device__ __half g_Xlo[3][SEQ * DMODEL];
__device__ __half g_Whi[4][DMODEL * DMODEL]; // Wq,Wk,Wv,Wo as [N][K]
__device__ __half g_Wlo[4][DMODEL * DMODEL];
__device__ __half g_Phi[3][SEQ * DMODEL];    // projected q,k,v (q pre-scaled)
__device__ __half g_Plo[3][SEQ * DMODEL];
__device__ __half g_Ohi[SEQ * DMODEL];       // concat (attention out)
__device__ __half g_Olo[SEQ * DMODEL];

#define ONESH2 0x3C003C00u   // {1.0h, 1.0h}

// ---------------------------------------------------------------------------
// Helpers
// ---------------------------------------------------------------------------
__device__ __forceinline__ uint32_t smem_u32(const void* p) {
    uint32_t a;
    asm("{ .reg .u64 t; cvta.to.shared.u64 t, %1; cvt.u32.u64 %0, t; }" : "=r"(a) : "l"(p));
    return a;
}

#define CP16(dst, src) \
    asm volatile("cp.async.cg.shared.global [%0], [%1], 16;" :: "r"((uint32_t)(dst)), "l"(src) : "memory")
#define CP_COMMIT() asm volatile("cp.async.commit_group;" ::: "memory")
#define CP_WAIT0()  asm volatile("cp.async.wait_group 0;" ::: "memory")
#define CP_WAIT1()  asm volatile("cp.async.wait_group 1;" ::: "memory")

__device__ __forceinline__ void ldsm4(uint32_t* r, uint32_t addr) {
    asm volatile("ldmatrix.sync.aligned.m8n8.x4.shared.b16 {%0,%1,%2,%3}, [%4];"
                 : "=r"(r[0]), "=r"(r[1]), "=r"(r[2]), "=r"(r[3]) : "r"(addr));
}
__device__ __forceinline__ void ldsm4t(uint32_t* r, uint32_t addr) {
    asm volatile("ldmatrix.sync.aligned.m8n8.x4.trans.shared.b16 {%0,%1,%2,%3}, [%4];"
                 : "=r"(r[0]), "=r"(r[1]), "=r"(r[2]), "=r"(r[3]) : "r"(addr));
}
__device__ __forceinline__ void mma16816h(float* c, const uint32_t* a, uint32_t b0, uint32_t b1) {
    asm volatile("mma.sync.aligned.m16n8k16.row.col.f32.f16.f16.f32 "
                 "{%0,%1,%2,%3}, {%4,%5,%6,%7}, {%8,%9}, {%0,%1,%2,%3};"
                 : "+f"(c[0]), "+f"(c[1]), "+f"(c[2]), "+f"(c[3])
                 : "r"(a[0]), "r"(a[1]), "r"(a[2]), "r"(a[3]), "r"(b0), "r"(b1));
}

__device__ __forceinline__ uint32_t h2u(__half2 h) { return *reinterpret_cast<uint32_t*>(&h); }
__device__ __forceinline__ void split2h(float x, float& hf, float& lf) {
    hf = __half2float(__float2half_rn(x));
    lf = x - hf;
}
__device__ __forceinline__ void hilo_packh(float x, float y, uint32_t& ph, uint32_t& pl) {
    __half2 h = __floats2half2_rn(x, y);
    ph = h2u(h);
    float lx = x - __low2float(h);
    float ly = y - __high2float(h);
    pl = h2u(__floats2half2_rn(lx, ly));
}

// ldmatrix address generators, parametric row pitch P (bytes).
__device__ __forceinline__ uint32_t a_addr(uint32_t tb, int r0, int kb, int lane, int P) {
    int sub = lane >> 3, ll = lane & 7;
    return tb + (uint32_t)(r0 + ((sub & 1) << 3) + ll) * P + kb + ((sub >> 1) << 4);
}
__device__ __forceinline__ uint32_t b_addr(uint32_t tb, int n0, int kb, int lane, int P) {
    int sub = lane >> 3, ll = lane & 7;
    return tb + (uint32_t)(n0 + ((sub >> 1) << 3) + ll) * P + kb + ((sub & 1) << 4);
}
__device__ __forceinline__ uint32_t v_addr(uint32_t tb, int k0, int nb, int lane, int P) {
    int sub = lane >> 3, ll = lane & 7;
    return tb + (uint32_t)(k0 + ((sub & 1) << 3) + ll) * P + nb + ((sub >> 1) << 4);
}

// ---------------------------------------------------------------------------
// Conversion kernels
// ---------------------------------------------------------------------------
__global__ void conv_in_kernel(const float* __restrict__ Q, const float* __restrict__ K,
                               const float* __restrict__ V)
{
    int z = blockIdx.y;
    const float* src = (z == 0) ? Q : (z == 1) ? K : V;
    #pragma unroll
    for (int k = 0; k < 2; k++) {
        size_t i = ((size_t)blockIdx.x * 256 + threadIdx.x) * 4 + (size_t)k * (SEQ * DMODEL / 2);
        float4 v = *(const float4*)(src + i);
        uint32_t ph, pl;
        hilo_packh(v.x, v.y, ph, pl);
        *(uint32_t*)&g_Xhi[z][i] = ph; *(uint32_t*)&g_Xlo[z][i] = pl;
        hilo_packh(v.z, v.w, ph, pl);
        *(uint32_t*)&g_Xhi[z][i + 2] = ph; *(uint32_t*)&g_Xlo[z][i + 2] = pl;
    }
}

__device__ __forceinline__ void conv_w_body(const float* __restrict__ src,
                                            __half* __restrict__ dhi,
                                            __half* __restrict__ dlo,
                                            int R, int C, int bx, int by)
{
    __shared__ float t[64][65];
    int r0 = bx * 64, c0 = by * 64;
    int tid = threadIdx.x;
    #pragma unroll
    for (int i = 0; i < 16; i++) {
        int idx = tid + i * 256;
        int rr = idx >> 6, cc = idx & 63;
        t[cc][rr] = src[(size_t)(r0 + rr) * C + c0 + cc];
    }
    __syncthreads();
    #pragma unroll
    for (int i = 0; i < 16; i++) {
        int idx = tid + i * 256;
        int rr = idx >> 6, cc = idx & 63;
        float h, l;
        split2h(t[rr][cc], h, l);
        dhi[(size_t)(c0 + rr) * R + r0 + cc] = __float2half_rn(h);
        dlo[(size_t)(c0 + rr) * R + r0 + cc] = __float2half_rn(l);
    }
}

__global__ void conv_w3_kernel(const float* __restrict__ Wq, const float* __restrict__ Wk,
                               const float* __restrict__ Wv)
{
    int which = blockIdx.z >> 4, zz = blockIdx.z & 15;
    const float* src = (which == 0) ? Wq : (which == 1) ? Wk : Wv;
    conv_w_body(src + (size_t)zz * DMODEL * HDK,
                &g_Whi[which][(size_t)zz * DMODEL * HDK],
                &g_Wlo[which][(size_t)zz * DMODEL * HDK],
                1024, 64, blockIdx.x, 0);
}

__global__ void conv_wo_kernel(const float* __restrict__ Wo)
{
    conv_w_body(Wo, g_Whi[3], g_Wlo[3], 1024, 1024, blockIdx.x, blockIdx.y);
}

// ---------------------------------------------------------------------------
// HMMA fp16x3 GEMM: C = A[S][1024] * B^T ([N][K]) + bias (optional scale).
// CTA 128x128, 8 warps (warp 32x64), K-chunk 32, 2-stage cp.async, TPG=80.
// smem 81920 B -> 2 CTAs/SM. MMA issue reordered term-major (chain spacing 4).
// ---------------------------------------------------------------------------
#define TPG 80
#define G_MAT   (128 * TPG)    // 10240
#define G_STAGE (4 * G_MAT)    // 40960
#define G_SMEM  (2 * G_STAGE)  // 81920
#define G_NCHUNK 32

__device__ __forceinline__ void g_load_chunk(
    uint32_t st,
    const __half* __restrict__ Ahi, const __half* __restrict__ Alo,
    const __half* __restrict__ Bhi, const __half* __restrict__ Blo,
    int m0, int n0, int k0, int tid)
{
    const __half* srcs[4] = {Ahi, Alo, Bhi, Blo};
    #pragma unroll
    for (int i = 0; i < 8; i++) {
        int idx = tid + i * 256;           // 0..2047
        int mat = idx >> 9;
        int j = idx & 511;
        int r = j >> 2, c = j & 3;
        int row = ((mat < 2) ? m0 : n0) + r;
        CP16(st + mat * G_MAT + (uint32_t)r * TPG + c * 16,
             srcs[mat] + (size_t)row * DMODEL + k0 + c * 8);
    }
    CP_COMMIT();
}

__device__ __forceinline__ void g_compute_chunk(uint32_t st, int lane, int wr, int wc,
                                                float C[2][8][4])
{
    #pragma unroll
    for (int ks = 0; ks < 2; ks++) {
        int kb = ks * 32;
        uint32_t ah[2][4], al[2][4];
        #pragma unroll
        for (int mt = 0; mt < 2; mt++) {
            ldsm4(ah[mt], a_addr(st,         wr * 32 + mt * 16, kb, lane, TPG));
            ldsm4(al[mt], a_addr(st + G_MAT, wr * 32 + mt * 16, kb, lane, TPG));
        }
        #pragma unroll
        for (int nt2 = 0; nt2 < 4; nt2++) {
            uint32_t bh[4], bl[4];
            ldsm4(bh, b_addr(st + 2 * G_MAT, wc * 64 + nt2 * 16, kb, lane, TPG));
            ldsm4(bl, b_addr(st + 3 * G_MAT, wc * 64 + nt2 * 16, kb, lane, TPG));
            float* c00 = C[0][nt2 * 2]; float* c10 = C[1][nt2 * 2];
            float* c01 = C[0][nt2 * 2 + 1]; float* c11 = C[1][nt2 * 2 + 1];
            // term-major across 4 accumulators: dependent ops spaced by 4
            mma16816h(c00, ah[0], bh[0], bh[1]);
            mma16816h(c10, ah[1], bh[0], bh[1]);
            mma16816h(c01, ah[0], bh[2], bh[3]);
            mma16816h(c11, ah[1], bh[2], bh[3]);
            mma16816h(c00, ah[0], bl[0], bl[1]);
            mma16816h(c10, ah[1], bl[0], bl[1]);
            mma16816h(c01, ah[0], bl[2], bl[3]);
            mma16816h(c11, ah[1], bl[2], bl[3]);
            mma16816h(c00, al[0], bh[0], bh[1]);
            mma16816h(c10, al[1], bh[0], bh[1]);
            mma16816h(c01, al[0], bh[2], bh[3]);
            mma16816h(c11, al[1], bh[2], bh[3]);
        }
    }
}

template <int MODE>   // 0: write fp16 hi/lo (scaled), 1: write fp32
__device__ __forceinline__ void gemm_body(
    const __half* __restrict__ Ahi, const __half* __restrict__ Alo,
    const __half* __restrict__ Bhi, const __half* __restrict__ Blo,
    const float* __restrict__ bias, float oscale,
    __half* __restrict__ Chi, __half* __restrict__ Clo,
    float* __restrict__ Cf)
{
    extern __shared__ __align__(128) char smem[];
    uint32_t sb = smem_u32(smem);
    const int tid = threadIdx.x;
    const int wid = tid >> 5, lane = tid & 31;
    const int wr = wid & 3, wc = wid >> 2;
    const int m0 = blockIdx.x * 128, n0 = blockIdx.y * 128;

    float C[2][8][4];
    #pragma unroll
    for (int a = 0; a < 2; a++)
        #pragma unroll
        for (int b = 0; b < 8; b++)
            #pragma unroll
            for (int c = 0; c < 4; c++) C[a][b][c] = 0.f;

    g_load_chunk(sb, Ahi, Alo, Bhi, Blo, m0, n0, 0, tid);

    for (int i = 0; i < G_NCHUNK; i++) {
        if (i + 1 < G_NCHUNK) {
            g_load_chunk(sb + ((i + 1) & 1) * G_STAGE, Ahi, Alo, Bhi, Blo,
                         m0, n0, (i + 1) * 32, tid);
            CP_WAIT1();
        } else {
            CP_WAIT0();
        }
        __syncthreads();
        g_compute_chunk(sb + (i & 1) * G_STAGE, lane, wr, wc, C);
        __syncthreads();
    }

    const int gid = lane >> 2, tig = lane & 3;
    #pragma unroll
    for (int mt = 0; mt < 2; mt++) {
        int row0 = m0 + wr * 32 + mt * 16 + gid;
        #pragma unroll
        for (int nt = 0; nt < 8; nt++) {
            int col = n0 + wc * 64 + nt * 8 + tig * 2;
            float b0 = bias[col], b1 = bias[col + 1];
            float v00 = (C[mt][nt][0] + b0) * oscale, v01 = (C[mt][nt][1] + b1) * oscale;
            float v10 = (C[mt][nt][2] + b0) * oscale, v11 = (C[mt][nt][3] + b1) * oscale;
            if (MODE == 0) {
                uint32_t ph, pl;
                hilo_packh(v00, v01, ph, pl);
                *(uint32_t*)&Chi[(size_t)row0 * DMODEL + col] = ph;
                *(uint32_t*)&Clo[(size_t)row0 * DMODEL + col] = pl;
                hilo_packh(v10, v11, ph, pl);
                *(uint32_t*)&Chi[(size_t)(row0 + 8) * DMODEL + col] = ph;
                *(uint32_t*)&Clo[(size_t)(row0 + 8) * DMODEL + col] = pl;
            } else {
                *(float2*)&Cf[(size_t)row0 * DMODEL + col] = make_float2(v00, v01);
                *(float2*)&Cf[(size_t)(row0 + 8) * DMODEL + col] = make_float2(v10, v11);
            }
        }
    }
}

__global__ __launch_bounds__(256, 2)
void proj_gemm_kernel(const float* __restrict__ bq, const float* __restrict__ bk,
                      const float* __restrict__ bv)
{
    int z = blockIdx.z;
    const float* bias = (z == 0) ? bq : (z == 1) ? bk : bv;
    // fold softmax scale * log2(e) into q so attention exp input is raw score
    float oscale = (z == 0) ? 0.18033688011112042f : 1.0f;
    gemm_body<0>(g_Xhi[z], g_Xlo[z], g_Whi[z], g_Wlo[z], bias, oscale,
                 g_Phi[z], g_Plo[z], nullptr);
}

__global__ __launch_bounds__(256, 2)
void out_gemm_kernel(const float* __restrict__ bo, float* __restrict__ out)
{
    gemm_body<1>(g_Ohi, g_Olo, g_Whi[3], g_Wlo[3], bo, 1.0f, nullptr, nullptr, out);
}

// ---------------------------------------------------------------------------
// Flash attention, fp16. QK: fp16 hi/lo 3-term. P = h2exp2 (native f16x2, no
// packing). PV: 2-term (P exact fp16 x Vhi/Vlo). Row sums via MMA with ones.
// CTA = 128 q-rows x 1 head, 8 warps (m16n64), K/V double-buffered.
// ---------------------------------------------------------------------------
#define ATP 144
#define AKV_TILE (64 * ATP)
#define AQ_TILE  (128 * ATP)
#define A_QHI 0
#define A_QLO AQ_TILE
#define A_KV  (2 * AQ_TILE)
#define A_SMEM (2 * AQ_TILE + 2 * 4 * AKV_TILE)   // 110592

__device__ __forceinline__ void attn_load_kv(
    uint32_t st, const __half* __restrict__ khi, const __half* __restrict__ klo,
    const __half* __restrict__ vhi, const __half* __restrict__ vlo,
    int j0, int colBase, int tid)
{
    const __half* srcs[4] = {khi, klo, vhi, vlo};
    #pragma unroll
    for (int i = 0; i < 8; i++) {
        int idx = tid + i * 256;
        int mat = idx >> 9;
        int j = idx & 511;
        int r = j >> 3, c = j & 7;
        uint32_t so = (uint32_t)r * ATP + c * 16;
        CP16(st + mat * AKV_TILE + so,
             srcs[mat] + (size_t)(j0 + r) * DMODEL + colBase + c * 8);
    }
    CP_COMMIT();
}

__global__ __launch_bounds__(256, 2)
void attn_kernel()
{
    extern __shared__ __align__(128) char smem[];
    uint32_t sb = smem_u32(smem);
    const int tid = threadIdx.x;
    const int wid = tid >> 5, lane = tid & 31;
    const int gid = lane >> 2, tig = lane & 3;
    const int qt = blockIdx.x, h = blockIdx.y;
    const int r0 = qt * 128;
    const int colBase = h * HDK;

    const __half* qhi = g_Phi[0]; const __half* qlo = g_Plo[0];
    const __half* khi = g_Phi[1]; const __half* klo = g_Plo[1];
    const __half* vhi = g_Phi[2]; const __half* vlo = g_Plo[2];

    // Q tiles hi/lo
    #pragma unroll
    for (int i = 0; i < 8; i++) {
        int idx = tid + i * 256;
        int mat = idx >> 10;
        int j = idx & 1023;
        int r = j >> 3, c = j & 7;
        uint32_t so = (uint32_t)r * ATP + c * 16;
        CP16(sb + (mat ? A_QLO : A_QHI) + so,
             (mat ? qlo : qhi) + (size_t)(r0 + r) * DMODEL + colBase + c * 8);
    }
    CP_COMMIT();
    attn_load_kv(sb + A_KV, khi, klo, vhi, vlo, 0, colBase, tid);
    CP_WAIT1();                          // Q arrived
    __syncthreads();

    uint32_t qfh[4][4], qfl[4][4];
    #pragma unroll
    for (int ks = 0; ks < 4; ks++) {
        ldsm4(qfh[ks], a_addr(sb + A_QHI, wid * 16, ks * 32, lane, ATP));
        ldsm4(qfl[ks], a_addr(sb + A_QLO, wid * 16, ks * 32, lane, ATP));
    }

    float O[8][4];
    #pragma unroll
    for (int a = 0; a < 8; a++)
        #pragma unroll
        for (int b = 0; b < 4; b++) O[a][b] = 0.f;
    float Csum[4] = {0.f, 0.f, 0.f, 0.f};

    for (int jt = 0; jt < 32; jt++) {
        CP_WAIT0();
        __syncthreads();
        if (jt + 1 < 32)
            attn_load_kv(sb + A_KV + ((jt + 1) & 1) * (4 * AKV_TILE),
                         khi, klo, vhi, vlo, (jt + 1) * 64, colBase, tid);
        uint32_t stCur = sb + A_KV + (jt & 1) * (4 * AKV_TILE);

        // ---- scores (q pre-scaled by 0.125*log2e) ----
        float sc[8][4];
        #pragma unroll
        for (int a = 0; a < 8; a++)
            #pragma unroll
            for (int b = 0; b < 4; b++) sc[a][b] = 0.f;

        #pragma unroll
        for (int ks = 0; ks < 4; ks++) {
            int kb = ks * 32;
            #pragma unroll
            for (int nt2 = 0; nt2 < 4; nt2++) {
                uint32_t bh[4], bl[4];
                ldsm4(bh, b_addr(stCur,            nt2 * 16, kb, lane, ATP));
                ldsm4(bl, b_addr(stCur + AKV_TILE, nt2 * 16, kb, lane, ATP));
                float* s0 = sc[nt2 * 2]; float* s1 = sc[nt2 * 2 + 1];
                mma16816h(s0, qfh[ks], bh[0], bh[1]);
                mma16816h(s1, qfh[ks], bh[2], bh[3]);
                mma16816h(s0, qfh[ks], bl[0], bl[1]);
                mma16816h(s1, qfh[ks], bl[2], bl[3]);
                mma16816h(s0, qfl[ks], bh[0], bh[1]);
                mma16816h(s1, qfl[ks], bh[2], bh[3]);
            }
        }

        // ---- P = exp2(sc) directly in f16x2 (A-fragment layout) ----
        uint32_t p01[8], p23[8];
        #pragma unroll
        for (int nt = 0; nt < 8; nt++) {
            p01[nt] = h2u(h2exp2(__floats2half2_rn(sc[nt][0], sc[nt][1])));
            p23[nt] = h2u(h2exp2(__floats2half2_rn(sc[nt][2], sc[nt][3])));
        }

        // ---- PV (2 terms) + row-sum via ones-MMA ----
        #pragma unroll
        for (int kt = 0; kt < 4; kt++) {
            uint32_t p[4] = {p01[2*kt], p23[2*kt], p01[2*kt+1], p23[2*kt+1]};
            mma16816h(Csum, p, ONESH2, ONESH2);
            #pragma unroll
            for (int nt2 = 0; nt2 < 4; nt2++) {
                uint32_t vh[4], vl[4];
                ldsm4t(vh, v_addr(stCur + 2 * AKV_TILE, kt * 16, nt2 * 32, lane, ATP));
                ldsm4t(vl, v_addr(stCur + 3 * AKV_TILE, kt * 16, nt2 * 32, lane, ATP));
                mma16816h(O[nt2*2],   p, vh[0], vh[1]);
                mma16816h(O[nt2*2+1], p, vh[2], vh[3]);
                mma16816h(O[nt2*2],   p, vl[0], vl[1]);
                mma16816h(O[nt2*2+1], p, vl[2], vl[3]);
            }
        }
    }

    // Csum[0]: full row sum (row gid); Csum[2]: row gid+8. No shuffles needed.
    float inv0 = 1.f / Csum[0], inv1 = 1.f / Csum[2];
    int rowA = r0 + wid * 16 + gid;
    #pragma unroll
    for (int nt = 0; nt < 8; nt++) {
        int col = colBase + nt * 8 + tig * 2;
        uint32_t ph, pl;
        hilo_packh(O[nt][0] * inv0, O[nt][1] * inv0, ph, pl);
        *(uint32_t*)&g_Ohi[(size_t)rowA * DMODEL + col] = ph;
        *(uint32_t*)&g_Olo[(size_t)rowA * DMODEL + col] = pl;
        hilo_packh(O[nt][2] * inv1, O[nt][3] * inv1, ph, pl);
        *(uint32_t*)&g_Ohi[(size_t)(rowA + 8) * DMODEL + col] = ph;
        *(uint32_t*)&g_Olo[(size_t)(rowA + 8) * DMODEL + col] = pl;
    }
}

// ---------------------------------------------------------------------------
extern "C" void kernel_launch(void* const* d_in, const int* in_sizes, int n_in,
                              void* d_out, int out_size)
{
    const float* Q  = (const float*)d_in[0];
    const float* K  = (const float*)d_in[1];
    const float* V  = (const float*)d_in[2];
    const float* Wq = (const float*)d_in[3];
    const float* bq = (const float*)d_in[4];
    const float* Wk = (const float*)d_in[5];
    const float* bk = (const float*)d_in[6];
    const float* Wv = (const float*)d_in[7];
    const float* bv = (const float*)d_in[8];
    const float* Wo = (const float*)d_in[9];
    const float* bo = (const float*)d_in[10];
    float* out = (float*)d_out;

    cudaFuncSetAttribute(proj_gemm_kernel, cudaFuncAttributeMaxDynamicSharedMemorySize, G_SMEM);
    cudaFuncSetAttribute(out_gemm_kernel,  cudaFuncAttributeMaxDynamicSharedMemorySize, G_SMEM);
    cudaFuncSetAttribute(attn_kernel,      cudaFuncAttributeMaxDynamicSharedMemorySize, A_SMEM);

    conv_in_kernel<<<dim3(SEQ * DMODEL / 2048, 3), 256>>>(Q, K, V);
    conv_w3_kernel<<<dim3(16, 1, 48), 256>>>(Wq, Wk, Wv);
    conv_wo_kernel<<<dim3(16, 16, 1), 256>>>(Wo);

    proj_gemm_kernel<<<dim3(16, 8, 3), 256, G_SMEM>>>(bq, bk, bv);
    attn_kernel<<<dim3(SEQ / 128, NH), 256, A_SMEM>>>();
    out_gemm_kernel<<<dim3(16, 8), 256, G_SMEM>>>(bo, out);
}

// round 12
// speedup vs baseline: 5.7948x; 1.8245x over previous
#include <cuda_runtime.h>
#include <cuda_fp16.h>
#include <math.h>
#include <stdint.h>

#define SEQ 2048
#define DMODEL 1024
#define NH 16
#define HDK 64

// ---------------------------------------------------------------------------
// Scratch (__device__ globals).
// ---------------------------------------------------------------------------
__device__ __half g_Xhi[3][SEQ * DMODEL];    // inputs Q,K,V (hi)
__device__ __half g_Xlo[3][SEQ * DMODEL];    // inputs lo (used by V-proj only)
__device__ __half g_Wh[4][DMODEL * DMODEL];  // Wq,Wk,Wv,Wo as [N][K], single fp16
__device__ __half g_P[3][SEQ * DMODEL];      // projected q,k,v (q pre-scaled), single fp16
__device__ __half g_Ohi[SEQ * DMODEL];       // concat hi
__device__ __half g_Olo[SEQ * DMODEL];       // concat lo

#define ONESH2 0x3C003C00u   // {1.0h, 1.0h}

// ---------------------------------------------------------------------------
// Helpers
// ---------------------------------------------------------------------------
__device__ __forceinline__ uint32_t smem_u32(const void* p) {
    uint32_t a;
    asm("{ .reg .u64 t; cvta.to.shared.u64 t, %1; cvt.u32.u64 %0, t; }" : "=r"(a) : "l"(p));
    return a;
}

#define CP16(dst, src) \
    asm volatile("cp.async.cg.shared.global [%0], [%1], 16;" :: "r"((uint32_t)(dst)), "l"(src) : "memory")
#define CP_COMMIT() asm volatile("cp.async.commit_group;" ::: "memory")
#define CP_WAIT0()  asm volatile("cp.async.wait_group 0;" ::: "memory")
#define CP_WAIT1()  asm volatile("cp.async.wait_group 1;" ::: "memory")

__device__ __forceinline__ void ldsm4(uint32_t* r, uint32_t addr) {
    asm volatile("ldmatrix.sync.aligned.m8n8.x4.shared.b16 {%0,%1,%2,%3}, [%4];"
                 : "=r"(r[0]), "=r"(r[1]), "=r"(r[2]), "=r"(r[3]) : "r"(addr));
}
__device__ __forceinline__ void ldsm4t(uint32_t* r, uint32_t addr) {
    asm volatile("ldmatrix.sync.aligned.m8n8.x4.trans.shared.b16 {%0,%1,%2,%3}, [%4];"
                 : "=r"(r[0]), "=r"(r[1]), "=r"(r[2]), "=r"(r[3]) : "r"(addr));
}
__device__ __forceinline__ void mma16816h(float* c, const uint32_t* a, uint32_t b0, uint32_t b1) {
    asm volatile("mma.sync.aligned.m16n8k16.row.col.f32.f16.f16.f32 "
                 "{%0,%1,%2,%3}, {%4,%5,%6,%7}, {%8,%9}, {%0,%1,%2,%3};"
                 : "+f"(c[0]), "+f"(c[1]), "+f"(c[2]), "+f"(c[3])
                 : "r"(a[0]), "r"(a[1]), "r"(a[2]), "r"(a[3]), "r"(b0), "r"(b1));
}

__device__ __forceinline__ uint32_t h2u(__half2 h) { return *reinterpret_cast<uint32_t*>(&h); }
__device__ __forceinline__ void hilo_packh(float x, float y, uint32_t& ph, uint32_t& pl) {
    __half2 h = __floats2half2_rn(x, y);
    ph = h2u(h);
    float lx = x - __low2float(h);
    float ly = y - __high2float(h);
    pl = h2u(__floats2half2_rn(lx, ly));
}

// ldmatrix address generators, parametric row pitch P (bytes).
__device__ __forceinline__ uint32_t a_addr(uint32_t tb, int r0, int kb, int lane, int P) {
    int sub = lane >> 3, ll = lane & 7;
    return tb + (uint32_t)(r0 + ((sub & 1) << 3) + ll) * P + kb + ((sub >> 1) << 4);
}
__device__ __forceinline__ uint32_t b_addr(uint32_t tb, int n0, int kb, int lane, int P) {
    int sub = lane >> 3, ll = lane & 7;
    return tb + (uint32_t)(n0 + ((sub >> 1) << 3) + ll) * P + kb + ((sub & 1) << 4);
}
__device__ __forceinline__ uint32_t v_addr(uint32_t tb, int k0, int nb, int lane, int P) {
    int sub = lane >> 3, ll = lane & 7;
    return tb + (uint32_t)(k0 + ((sub & 1) << 3) + ll) * P + nb + ((sub >> 1) << 4);
}

// ---------------------------------------------------------------------------
// Conversion kernels
// ---------------------------------------------------------------------------
__global__ void conv_in_kernel(const float* __restrict__ Q, const float* __restrict__ K,
                               const float* __restrict__ V)
{
    int z = blockIdx.y;
    const float* src = (z == 0) ? Q : (z == 1) ? K : V;
    #pragma unroll
    for (int k = 0; k < 2; k++) {
        size_t i = ((size_t)blockIdx.x * 256 + threadIdx.x) * 4 + (size_t)k * (SEQ * DMODEL / 2);
        float4 v = *(const float4*)(src + i);
        uint32_t ph, pl;
        hilo_packh(v.x, v.y, ph, pl);
        *(uint32_t*)&g_Xhi[z][i] = ph; *(uint32_t*)&g_Xlo[z][i] = pl;
        hilo_packh(v.z, v.w, ph, pl);
        *(uint32_t*)&g_Xhi[z][i + 2] = ph; *(uint32_t*)&g_Xlo[z][i + 2] = pl;
    }
}

// Transpose + convert to single fp16: src [R][C] fp32 -> dst [C][R]
__device__ __forceinline__ void conv_w_body(const float* __restrict__ src,
                                            __half* __restrict__ dst,
                                            int R, int C, int bx, int by)
{
    __shared__ float t[64][65];
    int r0 = bx * 64, c0 = by * 64;
    int tid = threadIdx.x;
    #pragma unroll
    for (int i = 0; i < 16; i++) {
        int idx = tid + i * 256;
        int rr = idx >> 6, cc = idx & 63;
        t[cc][rr] = src[(size_t)(r0 + rr) * C + c0 + cc];
    }
    __syncthreads();
    #pragma unroll
    for (int i = 0; i < 16; i++) {
        int idx = tid + i * 256;
        int rr = idx >> 6, cc = idx & 63;
        dst[(size_t)(c0 + rr) * R + r0 + cc] = __float2half_rn(t[rr][cc]);
    }
}

__global__ void conv_w3_kernel(const float* __restrict__ Wq, const float* __restrict__ Wk,
                               const float* __restrict__ Wv)
{
    int which = blockIdx.z >> 4, zz = blockIdx.z & 15;
    const float* src = (which == 0) ? Wq : (which == 1) ? Wk : Wv;
    conv_w_body(src + (size_t)zz * DMODEL * HDK,
                &g_Wh[which][(size_t)zz * DMODEL * HDK], 1024, 64, blockIdx.x, 0);
}

__global__ void conv_wo_kernel(const float* __restrict__ Wo)
{
    conv_w_body(Wo, g_Wh[3], 1024, 1024, blockIdx.x, blockIdx.y);
}

// ---------------------------------------------------------------------------
// HMMA GEMM: C = A[S][1024] * B^T ([N][K]) + bias.
// NT=1: A_hi x B. NT=2: (A_hi + A_lo) x B, both fp32-accum into same C.
// CTA 128x128, 8 warps (warp 32x64), K-chunk 32, 2-stage cp.async, TPG=80.
// ---------------------------------------------------------------------------
#define TPG 80
#define G_MAT   (128 * TPG)    // 10240
#define G_STAGE (3 * G_MAT)    // 30720 (A_hi, A_lo, B slots; A_lo unused for NT1)
#define G_SMEM  (2 * G_STAGE)  // 61440
#define G_NCHUNK 32

template <int NT>
__device__ __forceinline__ void g_load_chunk(
    uint32_t st, const __half* __restrict__ Ahi, const __half* __restrict__ Alo,
    const __half* __restrict__ B, int m0, int n0, int k0, int tid)
{
    #pragma unroll
    for (int i = 0; i < 2; i++) {
        int j = tid + i * 256;
        int r = j >> 2, c = j & 3;
        CP16(st + (uint32_t)r * TPG + c * 16, Ahi + (size_t)(m0 + r) * DMODEL + k0 + c * 8);
    }
    if (NT == 2) {
        #pragma unroll
        for (int i = 0; i < 2; i++) {
            int j = tid + i * 256;
            int r = j >> 2, c = j & 3;
            CP16(st + G_MAT + (uint32_t)r * TPG + c * 16, Alo + (size_t)(m0 + r) * DMODEL + k0 + c * 8);
        }
    }
    #pragma unroll
    for (int i = 0; i < 2; i++) {
        int j = tid + i * 256;
        int r = j >> 2, c = j & 3;
        CP16(st + 2 * G_MAT + (uint32_t)r * TPG + c * 16, B + (size_t)(n0 + r) * DMODEL + k0 + c * 8);
    }
    CP_COMMIT();
}

template <int NT>
__device__ __forceinline__ void g_compute_chunk(uint32_t st, int lane, int wr, int wc,
                                                float C[2][8][4])
{
    #pragma unroll
    for (int ks = 0; ks < 2; ks++) {
        int kb = ks * 32;
        uint32_t ah[2][4], al[2][4];
        ldsm4(ah[0], a_addr(st, wr * 32,      kb, lane, TPG));
        ldsm4(ah[1], a_addr(st, wr * 32 + 16, kb, lane, TPG));
        if (NT == 2) {
            ldsm4(al[0], a_addr(st + G_MAT, wr * 32,      kb, lane, TPG));
            ldsm4(al[1], a_addr(st + G_MAT, wr * 32 + 16, kb, lane, TPG));
        }
        #pragma unroll
        for (int nt2 = 0; nt2 < 4; nt2++) {
            uint32_t bh[4];
            ldsm4(bh, b_addr(st + 2 * G_MAT, wc * 64 + nt2 * 16, kb, lane, TPG));
            float* c00 = C[0][nt2 * 2];     float* c10 = C[1][nt2 * 2];
            float* c01 = C[0][nt2 * 2 + 1]; float* c11 = C[1][nt2 * 2 + 1];
            mma16816h(c00, ah[0], bh[0], bh[1]);
            mma16816h(c10, ah[1], bh[0], bh[1]);
            mma16816h(c01, ah[0], bh[2], bh[3]);
            mma16816h(c11, ah[1], bh[2], bh[3]);
            if (NT == 2) {
                mma16816h(c00, al[0], bh[0], bh[1]);
                mma16816h(c10, al[1], bh[0], bh[1]);
                mma16816h(c01, al[0], bh[2], bh[3]);
                mma16816h(c11, al[1], bh[2], bh[3]);
            }
        }
    }
}

template <int NT, int MODE>   // MODE 0: fp16 single out (w/ scale), 1: fp32 out
__device__ __forceinline__ void gemm_body(
    const __half* __restrict__ Ahi, const __half* __restrict__ Alo,
    const __half* __restrict__ B, const float* __restrict__ bias, float oscale,
    __half* __restrict__ Ch, float* __restrict__ Cf)
{
    extern __shared__ __align__(128) char smem[];
    uint32_t sb = smem_u32(smem);
    const int tid = threadIdx.x;
    const int wid = tid >> 5, lane = tid & 31;
    const int wr = wid & 3, wc = wid >> 2;
    const int m0 = blockIdx.x * 128, n0 = blockIdx.y * 128;

    float C[2][8][4];
    #pragma unroll
    for (int a = 0; a < 2; a++)
        #pragma unroll
        for (int b = 0; b < 8; b++)
            #pragma unroll
            for (int c = 0; c < 4; c++) C[a][b][c] = 0.f;

    g_load_chunk<NT>(sb, Ahi, Alo, B, m0, n0, 0, tid);

    for (int i = 0; i < G_NCHUNK; i++) {
        if (i + 1 < G_NCHUNK) {
            g_load_chunk<NT>(sb + ((i + 1) & 1) * G_STAGE, Ahi, Alo, B,
                             m0, n0, (i + 1) * 32, tid);
            CP_WAIT1();
        } else {
            CP_WAIT0();
        }
        __syncthreads();
        g_compute_chunk<NT>(sb + (i & 1) * G_STAGE, lane, wr, wc, C);
        __syncthreads();
    }

    const int gid = lane >> 2, tig = lane & 3;
    #pragma unroll
    for (int mt = 0; mt < 2; mt++) {
        int row0 = m0 + wr * 32 + mt * 16 + gid;
        #pragma unroll
        for (int nt = 0; nt < 8; nt++) {
            int col = n0 + wc * 64 + nt * 8 + tig * 2;
            float b0 = bias[col], b1 = bias[col + 1];
            float v00 = (C[mt][nt][0] + b0) * oscale, v01 = (C[mt][nt][1] + b1) * oscale;
            float v10 = (C[mt][nt][2] + b0) * oscale, v11 = (C[mt][nt][3] + b1) * oscale;
            if (MODE == 0) {
                *(uint32_t*)&Ch[(size_t)row0 * DMODEL + col] = h2u(__floats2half2_rn(v00, v01));
                *(uint32_t*)&Ch[(size_t)(row0 + 8) * DMODEL + col] = h2u(__floats2half2_rn(v10, v11));
            } else {
                *(float2*)&Cf[(size_t)row0 * DMODEL + col] = make_float2(v00, v01);
                *(float2*)&Cf[(size_t)(row0 + 8) * DMODEL + col] = make_float2(v10, v11);
            }
        }
    }
}

__global__ __launch_bounds__(256, 2)
void proj_gemm_kernel(const float* __restrict__ bq, const float* __restrict__ bk,
                      const float* __restrict__ bv)
{
    int z = blockIdx.z;
    const float* bias = (z == 0) ? bq : (z == 1) ? bk : bv;
    float oscale = (z == 0) ? 0.18033688011112042f : 1.0f;  // fold 0.125*log2(e) into q
    if (z == 2)
        gemm_body<2, 0>(g_Xhi[2], g_Xlo[2], g_Wh[2], bias, oscale, g_P[2], nullptr);
    else
        gemm_body<1, 0>(g_Xhi[z], nullptr, g_Wh[z], bias, oscale, g_P[z], nullptr);
}

__global__ __launch_bounds__(256, 2)
void out_gemm_kernel(const float* __restrict__ bo, float* __restrict__ out)
{
    gemm_body<2, 1>(g_Ohi, g_Olo, g_Wh[3], bo, 1.0f, nullptr, out);
}

// ---------------------------------------------------------------------------
// Flash attention, single-term fp16 HMMA. q pre-scaled by 0.125*log2e.
// P = exp2f (fp32 MUFU) -> fp16. Row sums via ones-MMA (fp32 accum).
// CTA = 128 q-rows x 1 head, 8 warps (m16n64), K/V double-buffered.
// smem: Q 18432 + 2 stages x (K 9216 + V 9216) = 55296 -> 2+ CTAs/SM.
// ---------------------------------------------------------------------------
#define ATP 144
#define AK_TILE (64 * ATP)       // 9216
#define AQ_TILE (128 * ATP)      // 18432
#define A_KV    AQ_TILE
#define A_STAGE (2 * AK_TILE)    // 18432
#define A_SMEM  (AQ_TILE + 2 * A_STAGE)   // 55296

__device__ __forceinline__ void attn_load_kv(
    uint32_t st, const __half* __restrict__ kk, const __half* __restrict__ vv,
    int j0, int colBase, int tid)
{
    #pragma unroll
    for (int i = 0; i < 4; i++) {
        int idx = tid + i * 256;          // 0..1023
        int mat = idx >> 9;               // 0=K, 1=V
        int j = idx & 511;
        int r = j >> 3, c = j & 7;
        uint32_t so = (uint32_t)r * ATP + c * 16;
        CP16(st + mat * AK_TILE + so,
             (mat ? vv : kk) + (size_t)(j0 + r) * DMODEL + colBase + c * 8);
    }
    CP_COMMIT();
}

__global__ __launch_bounds__(256, 2)
void attn_kernel()
{
    extern __shared__ __align__(128) char smem[];
    uint32_t sb = smem_u32(smem);
    const int tid = threadIdx.x;
    const int wid = tid >> 5, lane = tid & 31;
    const int gid = lane >> 2, tig = lane & 3;
    const int qt = blockIdx.x, h = blockIdx.y;
    const int r0 = qt * 128;
    const int colBase = h * HDK;

    const __half* qp = g_P[0];
    const __half* kp = g_P[1];
    const __half* vp = g_P[2];

    // Q tile (single fp16)
    #pragma unroll
    for (int i = 0; i < 4; i++) {
        int idx = tid + i * 256;
        int r = idx >> 3, c = idx & 7;
        uint32_t so = (uint32_t)r * ATP + c * 16;
        CP16(sb + so, qp + (size_t)(r0 + r) * DMODEL + colBase + c * 8);
    }
    CP_COMMIT();
    attn_load_kv(sb + A_KV, kp, vp, 0, colBase, tid);
    CP_WAIT1();                          // Q arrived
    __syncthreads();

    uint32_t qf[4][4];
    #pragma unroll
    for (int ks = 0; ks < 4; ks++)
        ldsm4(qf[ks], a_addr(sb, wid * 16, ks * 32, lane, ATP));

    float O[8][4];
    #pragma unroll
    for (int a = 0; a < 8; a++)
        #pragma unroll
        for (int b = 0; b < 4; b++) O[a][b] = 0.f;
    float Csum[4] = {0.f, 0.f, 0.f, 0.f};

    for (int jt = 0; jt < 32; jt++) {
        CP_WAIT0();
        __syncthreads();
        if (jt + 1 < 32)
            attn_load_kv(sb + A_KV + ((jt + 1) & 1) * A_STAGE,
                         kp, vp, (jt + 1) * 64, colBase, tid);
        uint32_t stCur = sb + A_KV + (jt & 1) * A_STAGE;

        // ---- scores (1-term) ----
        float sc[8][4];
        #pragma unroll
        for (int a = 0; a < 8; a++)
            #pragma unroll
            for (int b = 0; b < 4; b++) sc[a][b] = 0.f;

        #pragma unroll
        for (int ks = 0; ks < 4; ks++) {
            int kb = ks * 32;
            #pragma unroll
            for (int nt2 = 0; nt2 < 4; nt2++) {
                uint32_t bh[4];
                ldsm4(bh, b_addr(stCur, nt2 * 16, kb, lane, ATP));
                mma16816h(sc[nt2 * 2],     qf[ks], bh[0], bh[1]);
                mma16816h(sc[nt2 * 2 + 1], qf[ks], bh[2], bh[3]);
            }
        }

        // ---- P = exp2(sc), fp32 MUFU precision, packed to fp16 ----
        uint32_t p01[8], p23[8];
        #pragma unroll
        for (int nt = 0; nt < 8; nt++) {
            p01[nt] = h2u(__floats2half2_rn(exp2f(sc[nt][0]), exp2f(sc[nt][1])));
            p23[nt] = h2u(__floats2half2_rn(exp2f(sc[nt][2]), exp2f(sc[nt][3])));
        }

        // ---- PV (1-term) + row-sum via ones-MMA ----
        #pragma unroll
        for (int kt = 0; kt < 4; kt++) {
            uint32_t p[4] = {p01[2 * kt], p23[2 * kt], p01[2 * kt + 1], p23[2 * kt + 1]};
            mma16816h(Csum, p, ONESH2, ONESH2);
            #pragma unroll
            for (int nt2 = 0; nt2 < 4; nt2++) {
                uint32_t vh[4];
                ldsm4t(vh, v_addr(stCur + AK_TILE, kt * 16, nt2 * 32, lane, ATP));
                mma16816h(O[nt2 * 2],     p, vh[0], vh[1]);
                mma16816h(O[nt2 * 2 + 1], p, vh[2], vh[3]);
            }
        }
    }

    float inv0 = 1.f / Csum[0], inv1 = 1.f / Csum[2];
    int rowA = r0 + wid * 16 + gid;
    #pragma unroll
    for (int nt = 0; nt < 8; nt++) {
        int col = colBase + nt * 8 + tig * 2;
        uint32_t ph, pl;
        hilo_packh(O[nt][0] * inv0, O[nt][1] * inv0, ph, pl);
        *(uint32_t*)&g_Ohi[(size_t)rowA * DMODEL + col] = ph;
        *(uint32_t*)&g_Olo[(size_t)rowA * DMODEL + col] = pl;
        hilo_packh(O[nt][2] * inv1, O[nt][3] * inv1, ph, pl);
        *(uint32_t*)&g_Ohi[(size_t)(rowA + 8) * DMODEL + col] = ph;
        *(uint32_t*)&g_Olo[(size_t)(rowA + 8) * DMODEL + col] = pl;
    }
}

// ---------------------------------------------------------------------------
extern "C" void kernel_launch(void* const* d_in, const int* in_sizes, int n_in,
                              void* d_out, int out_size)
{
    const float* Q  = (const float*)d_in[0];
    const float* K  = (const float*)d_in[1];
    const float* V  = (const float*)d_in[2];
    const float* Wq = (const float*)d_in[3];
    const float* bq = (const float*)d_in[4];
    const float* Wk = (const float*)d_in[5];
    const float* bk = (const float*)d_in[6];
    const float* Wv = (const float*)d_in[7];
    const float* bv = (const float*)d_in[8];
    const float* Wo = (const float*)d_in[9];
    const float* bo = (const float*)d_in[10];
    float* out = (float*)d_out;

    cudaFuncSetAttribute(proj_gemm_kernel, cudaFuncAttributeMaxDynamicSharedMemorySize, G_SMEM);
    cudaFuncSetAttribute(out_gemm_kernel,  cudaFuncAttributeMaxDynamicSharedMemorySize, G_SMEM);
    cudaFuncSetAttribute(attn_kernel,      cudaFuncAttributeMaxDynamicSharedMemorySize, A_SMEM);

    conv_in_kernel<<<dim3(SEQ * DMODEL / 2048, 3), 256>>>(Q, K, V);
    conv_w3_kernel<<<dim3(16, 1, 48), 256>>>(Wq, Wk, Wv);
    conv_wo_kernel<<<dim3(16, 16, 1), 256>>>(Wo);

    proj_gemm_kernel<<<dim3(16, 8, 3), 256, G_SMEM>>>(bq, bk, bv);
    attn_kernel<<<dim3(SEQ / 128, NH), 256, A_SMEM>>>();
    out_gemm_kernel<<<dim3(16, 8), 256, G_SMEM>>>(bo, out);
}